// round 1
// baseline (speedup 1.0000x reference)
#include <cuda_runtime.h>
#include <math.h>

#define BATCH 8
#define DM 256
#define NH 4
#define HD 64
#define SEQ 2048
#define BH (BATCH*NH)

// Scratch (allocation-free: device globals)
__device__ float g_q[BATCH*DM*SEQ];
__device__ float g_k[BATCH*DM*SEQ];
__device__ float g_v[BATCH*DM*SEQ];
__device__ float g_x[BATCH*DM*SEQ];
__device__ float g_s[(size_t)BH*SEQ*SEQ];   // 512 MiB score matrix

// Polynomial exp: avoids MUFU bottleneck (rt_SMSP=8 -> only 0.5 exp/cyc/SM).
// x <= 0 expected; clamp for safety. |err| ~ 2.4e-6 relative.
__device__ __forceinline__ float fast_exp(float x) {
    x = fmaxf(x, -87.0f);
    float y = x * 1.4426950408889634f;     // log2(e)
    float n = rintf(y);
    float f = y - n;                        // f in [-0.5, 0.5]
    float p = 0.0013333558f;
    p = fmaf(p, f, 0.0096181291f);
    p = fmaf(p, f, 0.0555041087f);
    p = fmaf(p, f, 0.2402265070f);
    p = fmaf(p, f, 0.6931471806f);
    p = fmaf(p, f, 1.0f);
    int e = (int)n;
    float s = __int_as_float((e + 127) << 23);
    return p * s;
}

// ---------------------------------------------------------------------------
// Projection: C[b][o][n] = sum_i W[o][i]*X[b][i][n] + bias[o]
// grid (SEQ/64, DM/64, BATCH), 256 threads, 64x64 tile, 4x4 micro-tile.
// ---------------------------------------------------------------------------
__global__ __launch_bounds__(256)
void proj_kernel(const float* __restrict__ W, const float* __restrict__ bias,
                 const float* __restrict__ X, float* __restrict__ C) {
    __shared__ float Ws[16][64];   // [i][o]
    __shared__ float Xs[16][64];   // [i][n]
    const int n0 = blockIdx.x * 64;
    const int o0 = blockIdx.y * 64;
    const int b  = blockIdx.z;
    const float* Xb = X + (size_t)b * DM * SEQ;
    float* Cb = C + (size_t)b * DM * SEQ;
    const int tid = threadIdx.x;
    const int tx = tid & 15, ty = tid >> 4;
    const int wo = tid >> 2;            // 0..63
    const int wi = (tid & 3) * 4;       // 0,4,8,12
    const int xr = tid >> 6;            // 0..3
    const int xc = tid & 63;
    float acc[4][4] = {};
    for (int k0 = 0; k0 < DM; k0 += 16) {
        float4 wv = *(const float4*)&W[(o0 + wo) * DM + k0 + wi];
        Ws[wi+0][wo] = wv.x; Ws[wi+1][wo] = wv.y;
        Ws[wi+2][wo] = wv.z; Ws[wi+3][wo] = wv.w;
        #pragma unroll
        for (int r = 0; r < 4; r++)
            Xs[xr + 4*r][xc] = Xb[(size_t)(k0 + xr + 4*r) * SEQ + n0 + xc];
        __syncthreads();
        #pragma unroll
        for (int kk = 0; kk < 16; kk++) {
            float4 a  = *(const float4*)&Ws[kk][ty*4];
            float4 bb = *(const float4*)&Xs[kk][tx*4];
            float av[4] = {a.x, a.y, a.z, a.w};
            float bv[4] = {bb.x, bb.y, bb.z, bb.w};
            #pragma unroll
            for (int i = 0; i < 4; i++)
                #pragma unroll
                for (int j = 0; j < 4; j++)
                    acc[i][j] = fmaf(av[i], bv[j], acc[i][j]);
        }
        __syncthreads();
    }
    #pragma unroll
    for (int i = 0; i < 4; i++) {
        float bi = bias[o0 + ty*4 + i];
        float4 out = make_float4(acc[i][0]+bi, acc[i][1]+bi, acc[i][2]+bi, acc[i][3]+bi);
        *(float4*)&Cb[(size_t)(o0 + ty*4 + i) * SEQ + n0 + tx*4] = out;
    }
}

// ---------------------------------------------------------------------------
// Scores: S[bh][n][m] = 0.125 * sum_d Q[b][4d+h][n] * K[b][4d+h][m]
// grid (SEQ/64 m, SEQ/64 n, BH), 256 threads, K=64 fully resident in smem.
// ---------------------------------------------------------------------------
__global__ __launch_bounds__(256)
void score_kernel(const float* __restrict__ Q, const float* __restrict__ K,
                  float* __restrict__ S) {
    __shared__ float Qs[64][64];  // [d][n]
    __shared__ float Ks[64][64];  // [d][m]
    const int m0 = blockIdx.x * 64;
    const int n0 = blockIdx.y * 64;
    const int bh = blockIdx.z;
    const int b = bh >> 2, h = bh & 3;
    const float* Qb = Q + (size_t)b*DM*SEQ + h*SEQ;
    const float* Kb = K + (size_t)b*DM*SEQ + h*SEQ;
    const int tid = threadIdx.x;
    #pragma unroll
    for (int r = 0; r < 16; r++) {
        int idx = tid + 256*r;
        int d = idx >> 6, c = idx & 63;
        Qs[d][c] = Qb[(size_t)(d << 2)*SEQ + n0 + c];
        Ks[d][c] = Kb[(size_t)(d << 2)*SEQ + m0 + c];
    }
    __syncthreads();
    const int tx = tid & 15, ty = tid >> 4;
    float acc[4][4] = {};
    #pragma unroll
    for (int d = 0; d < 64; d++) {
        float4 a  = *(const float4*)&Qs[d][ty*4];
        float4 bb = *(const float4*)&Ks[d][tx*4];
        float av[4] = {a.x, a.y, a.z, a.w};
        float bv[4] = {bb.x, bb.y, bb.z, bb.w};
        #pragma unroll
        for (int i = 0; i < 4; i++)
            #pragma unroll
            for (int j = 0; j < 4; j++)
                acc[i][j] = fmaf(av[i], bv[j], acc[i][j]);
    }
    float* Sb = S + (size_t)bh*SEQ*SEQ;
    #pragma unroll
    for (int i = 0; i < 4; i++) {
        float4 out = make_float4(acc[i][0]*0.125f, acc[i][1]*0.125f,
                                 acc[i][2]*0.125f, acc[i][3]*0.125f);
        *(float4*)&Sb[(size_t)(n0 + ty*4 + i)*SEQ + m0 + tx*4] = out;
    }
}

// ---------------------------------------------------------------------------
// Softmax over last dim (in place). One 256-thread block per row (8 vals/thread).
// ---------------------------------------------------------------------------
__global__ __launch_bounds__(256)
void softmax_kernel(float* __restrict__ S) {
    float* p = S + (size_t)blockIdx.x * SEQ;
    const int tid = threadIdx.x;
    __shared__ float red[8];
    float v[8];
    float mx = -3.4e38f;
    #pragma unroll
    for (int i = 0; i < 8; i++) { v[i] = p[tid + 256*i]; mx = fmaxf(mx, v[i]); }
    #pragma unroll
    for (int o = 16; o; o >>= 1) mx = fmaxf(mx, __shfl_xor_sync(0xffffffffu, mx, o));
    if ((tid & 31) == 0) red[tid >> 5] = mx;
    __syncthreads();
    mx = red[0];
    #pragma unroll
    for (int i = 1; i < 8; i++) mx = fmaxf(mx, red[i]);
    float sum = 0.f;
    #pragma unroll
    for (int i = 0; i < 8; i++) { v[i] = fast_exp(v[i] - mx); sum += v[i]; }
    #pragma unroll
    for (int o = 16; o; o >>= 1) sum += __shfl_xor_sync(0xffffffffu, sum, o);
    __syncthreads();
    if ((tid & 31) == 0) red[tid >> 5] = sum;
    __syncthreads();
    sum = 0.f;
    #pragma unroll
    for (int i = 0; i < 8; i++) sum += red[i];
    float inv = 1.0f / sum;
    #pragma unroll
    for (int i = 0; i < 8; i++) p[tid + 256*i] = v[i] * inv;
}

// ---------------------------------------------------------------------------
// PV: X[b][4d+h][n] = sum_m P[bh][n][m] * V[b][4d+h][m]
// grid (SEQ/64 n, BH), 256 threads, 64(d)x64(n) tile, K=SEQ in steps of 16.
// ---------------------------------------------------------------------------
__global__ __launch_bounds__(256)
void pv_kernel(const float* __restrict__ S, const float* __restrict__ V,
               float* __restrict__ X) {
    __shared__ float Vs[16][64];  // [m][d]
    __shared__ float Ps[16][64];  // [m][n]
    const int n0 = blockIdx.x * 64;
    const int bh = blockIdx.y;
    const int b = bh >> 2, h = bh & 3;
    const float* Vb = V + (size_t)b*DM*SEQ + h*SEQ;
    const float* Sb = S + (size_t)bh*SEQ*SEQ;
    const int tid = threadIdx.x;
    const int tx = tid & 15, ty = tid >> 4;
    const int lr = tid >> 2;          // 0..63
    const int lc = (tid & 3) * 4;     // 0,4,8,12
    float acc[4][4] = {};
    for (int m0 = 0; m0 < SEQ; m0 += 16) {
        float4 vv = *(const float4*)&Vb[(size_t)(lr << 2)*SEQ + m0 + lc];
        float4 pv = *(const float4*)&Sb[(size_t)(n0 + lr)*SEQ + m0 + lc];
        __syncthreads();
        Vs[lc+0][lr] = vv.x; Vs[lc+1][lr] = vv.y;
        Vs[lc+2][lr] = vv.z; Vs[lc+3][lr] = vv.w;
        Ps[lc+0][lr] = pv.x; Ps[lc+1][lr] = pv.y;
        Ps[lc+2][lr] = pv.z; Ps[lc+3][lr] = pv.w;
        __syncthreads();
        #pragma unroll
        for (int mm = 0; mm < 16; mm++) {
            float4 a  = *(const float4*)&Vs[mm][ty*4];
            float4 bb = *(const float4*)&Ps[mm][tx*4];
            float av[4] = {a.x, a.y, a.z, a.w};
            float bv[4] = {bb.x, bb.y, bb.z, bb.w};
            #pragma unroll
            for (int i = 0; i < 4; i++)
                #pragma unroll
                for (int j = 0; j < 4; j++)
                    acc[i][j] = fmaf(av[i], bv[j], acc[i][j]);
        }
    }
    float* Xb = X + (size_t)b*DM*SEQ + h*SEQ;
    #pragma unroll
    for (int i = 0; i < 4; i++) {
        float4 out = make_float4(acc[i][0], acc[i][1], acc[i][2], acc[i][3]);
        *(float4*)&Xb[(size_t)((ty*4 + i) << 2)*SEQ + n0 + tx*4] = out;
    }
}

// ---------------------------------------------------------------------------
extern "C" void kernel_launch(void* const* d_in, const int* in_sizes, int n_in,
                              void* d_out, int out_size) {
    const float* query = (const float*)d_in[0];
    const float* key   = (const float*)d_in[1];
    const float* value = (const float*)d_in[2];
    const float* Wq = (const float*)d_in[3];
    const float* bq = (const float*)d_in[4];
    const float* Wk = (const float*)d_in[5];
    const float* bk = (const float*)d_in[6];
    const float* Wv = (const float*)d_in[7];
    const float* bv = (const float*)d_in[8];
    const float* Wm = (const float*)d_in[9];
    const float* bm = (const float*)d_in[10];

    float *q, *k, *v, *x, *s;
    cudaGetSymbolAddress((void**)&q, g_q);
    cudaGetSymbolAddress((void**)&k, g_k);
    cudaGetSymbolAddress((void**)&v, g_v);
    cudaGetSymbolAddress((void**)&x, g_x);
    cudaGetSymbolAddress((void**)&s, g_s);

    dim3 pjGrid(SEQ/64, DM/64, BATCH);
    proj_kernel<<<pjGrid, 256>>>(Wq, bq, query, q);
    proj_kernel<<<pjGrid, 256>>>(Wk, bk, key,   k);
    proj_kernel<<<pjGrid, 256>>>(Wv, bv, value, v);

    score_kernel<<<dim3(SEQ/64, SEQ/64, BH), 256>>>(q, k, s);
    softmax_kernel<<<BH*SEQ, 256>>>(s);
    pv_kernel<<<dim3(SEQ/64, BH), 256>>>(s, v, x);

    proj_kernel<<<pjGrid, 256>>>(Wm, bm, x, (float*)d_out);
}

// round 4
// speedup vs baseline: 2.0955x; 2.0955x over previous
#include <cuda_runtime.h>
#include <cuda_bf16.h>
#include <cstdint>

#define BATCH 8
#define DM 256
#define NH 4
#define HD 64
#define SEQ 2048
#define BH (BATCH*NH)

typedef unsigned short u16;

// Q,K: [bh][n][d] hi/lo bf16 ; V: [bh][d][m] hi/lo ; X: [b][c][n] fp32
__device__ __nv_bfloat16 g_qh[(size_t)BH*SEQ*HD];
__device__ __nv_bfloat16 g_ql[(size_t)BH*SEQ*HD];
__device__ __nv_bfloat16 g_kh[(size_t)BH*SEQ*HD];
__device__ __nv_bfloat16 g_kl[(size_t)BH*SEQ*HD];
__device__ __nv_bfloat16 g_vh[(size_t)BH*HD*SEQ];
__device__ __nv_bfloat16 g_vl[(size_t)BH*HD*SEQ];
__device__ float         g_x [(size_t)BATCH*DM*SEQ];

__device__ __forceinline__ float ex2f(float x) {
    float r; asm("ex2.approx.f32 %0, %1;" : "=f"(r) : "f"(x)); return r;
}
// pack v0->low bf16, v1->high bf16; plus residual pack
__device__ __forceinline__ void split2(float v0, float v1, uint32_t& hp, uint32_t& lp) {
    asm("cvt.rn.bf16x2.f32 %0, %1, %2;" : "=r"(hp) : "f"(v1), "f"(v0));
    float f0 = __uint_as_float(hp << 16);
    float f1 = __uint_as_float(hp & 0xffff0000u);
    asm("cvt.rn.bf16x2.f32 %0, %1, %2;" : "=r"(lp) : "f"(v1 - f1), "f"(v0 - f0));
}
__device__ __forceinline__ void mma16816(float* d, const uint32_t* a, uint32_t b0, uint32_t b1) {
    asm volatile("mma.sync.aligned.m16n8k16.row.col.f32.bf16.bf16.f32 "
                 "{%0,%1,%2,%3}, {%4,%5,%6,%7}, {%8,%9}, {%0,%1,%2,%3};\n"
                 : "+f"(d[0]), "+f"(d[1]), "+f"(d[2]), "+f"(d[3])
                 : "r"(a[0]), "r"(a[1]), "r"(a[2]), "r"(a[3]), "r"(b0), "r"(b1));
}

// ---------------------------------------------------------------------------
// Projection: C[b][o][n] = sum_i W[o][i]*X[b][i][n] + bias[o]
// MODE 0: fp32 [b][o][n]; MODE 1: hi/lo bf16 [bh][n][d]; MODE 2: hi/lo [bh][d][m]
// ---------------------------------------------------------------------------
template<int MODE>
__global__ __launch_bounds__(256)
void proj_kernel(const float* __restrict__ W, const float* __restrict__ bias,
                 const float* __restrict__ X, float* __restrict__ C0,
                 __nv_bfloat16* __restrict__ Ch, __nv_bfloat16* __restrict__ Cl) {
    __shared__ float Ws[16][64];
    __shared__ float Xs[16][64];
    __shared__ u16 Th[64][68];
    __shared__ u16 Tl[64][68];
    const int n0 = blockIdx.x * 64, o0 = blockIdx.y * 64, b = blockIdx.z;
    const float* Xb = X + (size_t)b * DM * SEQ;
    const int tid = threadIdx.x;
    const int tx = tid & 15, ty = tid >> 4;
    const int wo = tid >> 2, wi = (tid & 3) * 4;
    const int xr = tid >> 6, xc = tid & 63;
    float acc[4][4] = {};
    for (int k0 = 0; k0 < DM; k0 += 16) {
        float4 wv = *(const float4*)&W[(o0 + wo) * DM + k0 + wi];
        Ws[wi+0][wo] = wv.x; Ws[wi+1][wo] = wv.y;
        Ws[wi+2][wo] = wv.z; Ws[wi+3][wo] = wv.w;
        #pragma unroll
        for (int r = 0; r < 4; r++)
            Xs[xr + 4*r][xc] = Xb[(size_t)(k0 + xr + 4*r) * SEQ + n0 + xc];
        __syncthreads();
        #pragma unroll
        for (int kk = 0; kk < 16; kk++) {
            float4 a  = *(const float4*)&Ws[kk][ty*4];
            float4 bb = *(const float4*)&Xs[kk][tx*4];
            float av[4] = {a.x, a.y, a.z, a.w};
            float bv[4] = {bb.x, bb.y, bb.z, bb.w};
            #pragma unroll
            for (int i = 0; i < 4; i++)
                #pragma unroll
                for (int j = 0; j < 4; j++)
                    acc[i][j] = fmaf(av[i], bv[j], acc[i][j]);
        }
        __syncthreads();
    }
    if (MODE == 0) {
        float* Cb = C0 + (size_t)b * DM * SEQ;
        #pragma unroll
        for (int i = 0; i < 4; i++) {
            float bi = bias[o0 + ty*4 + i];
            float4 o = make_float4(acc[i][0]+bi, acc[i][1]+bi, acc[i][2]+bi, acc[i][3]+bi);
            *(float4*)&Cb[(size_t)(o0 + ty*4 + i) * SEQ + n0 + tx*4] = o;
        }
    } else if (MODE == 1) {
        #pragma unroll
        for (int i = 0; i < 4; i++) {
            float bi = bias[o0 + ty*4 + i];
            #pragma unroll
            for (int j = 0; j < 4; j++) {
                float v = acc[i][j] + bi;
                __nv_bfloat16 hb = __float2bfloat16(v);
                __nv_bfloat16 lb = __float2bfloat16(v - __bfloat162float(hb));
                Th[tx*4+j][ty*4+i] = __bfloat16_as_ushort(hb);
                Tl[tx*4+j][ty*4+i] = __bfloat16_as_ushort(lb);
            }
        }
        __syncthreads();
        int n = tid & 63, hh = tid >> 6;
        u16 bh_[16], bl_[16];
        #pragma unroll
        for (int dd = 0; dd < 16; dd++) {
            bh_[dd] = Th[n][4*dd + hh];
            bl_[dd] = Tl[n][4*dd + hh];
        }
        size_t dst = ((size_t)(b*NH + hh) * SEQ + n0 + n) * HD + (o0 >> 2);
        *(uint4*)((u16*)Ch + dst)     = *(uint4*)bh_;
        *(uint4*)((u16*)Ch + dst + 8) = *(uint4*)(bh_ + 8);
        *(uint4*)((u16*)Cl + dst)     = *(uint4*)bl_;
        *(uint4*)((u16*)Cl + dst + 8) = *(uint4*)(bl_ + 8);
    } else {
        #pragma unroll
        for (int i = 0; i < 4; i++) {
            int o = o0 + ty*4 + i;
            float bi = bias[o];
            size_t base = ((size_t)(b*NH + (o & 3)) * HD + (o >> 2)) * SEQ + n0 + tx*4;
            uint32_t h01, l01, h23, l23;
            split2(acc[i][0]+bi, acc[i][1]+bi, h01, l01);
            split2(acc[i][2]+bi, acc[i][3]+bi, h23, l23);
            *(uint2*)((u16*)Ch + base) = make_uint2(h01, h23);
            *(uint2*)((u16*)Cl + base) = make_uint2(l01, l23);
        }
    }
}

// ---------------------------------------------------------------------------
// Fused flash attention (no-max softmax), mma.sync bf16 3-term split.
// 256 threads = 8 warps x 16 q-rows. Grid (SEQ/128, BH).
// ---------------------------------------------------------------------------
#define KPITCH 144
#define VPITCH 272
#define SBUF   18432

__global__ __launch_bounds__(256)
void flash_kernel(const __nv_bfloat16* __restrict__ qh, const __nv_bfloat16* __restrict__ ql,
                  const __nv_bfloat16* __restrict__ kh, const __nv_bfloat16* __restrict__ kl,
                  const __nv_bfloat16* __restrict__ vh, const __nv_bfloat16* __restrict__ vl,
                  float* __restrict__ X) {
    __shared__ __align__(16) char smA[SBUF];
    __shared__ __align__(16) char smB[SBUF];
    const int n0 = blockIdx.x * 128;
    const int bh = blockIdx.y;
    const int b = bh >> 2, h = bh & 3;
    const int t = threadIdx.x;
    const int w = t >> 5, l = t & 31;
    const int g = l >> 2, tt = l & 3;
    const float SCL = 0.125f * 1.44269504088896f;

    // stage Q [128 n][64 d], build A-fragments in registers
    {
        const int m = t >> 1, half = (t & 1) * 32;
        const u16* ph = (const u16*)qh + ((size_t)bh*SEQ + n0 + m) * HD + half;
        const u16* pl = (const u16*)ql + ((size_t)bh*SEQ + n0 + m) * HD + half;
        #pragma unroll
        for (int u = 0; u < 4; u++) {
            *(uint4*)(smA + m*KPITCH + half*2 + 16*u) = *(const uint4*)(ph + 8*u);
            *(uint4*)(smB + m*KPITCH + half*2 + 16*u) = *(const uint4*)(pl + 8*u);
        }
    }
    __syncthreads();
    uint32_t qa_h[4][4], qa_l[4][4];
    {
        const int r0 = (16*w + g) * KPITCH;
        #pragma unroll
        for (int j = 0; j < 4; j++) {
            const int c = (16*j + 2*tt) * 2;
            qa_h[j][0] = *(const uint32_t*)(smA + r0 + c);
            qa_h[j][1] = *(const uint32_t*)(smA + r0 + 8*KPITCH + c);
            qa_h[j][2] = *(const uint32_t*)(smA + r0 + c + 16);
            qa_h[j][3] = *(const uint32_t*)(smA + r0 + 8*KPITCH + c + 16);
            qa_l[j][0] = *(const uint32_t*)(smB + r0 + c);
            qa_l[j][1] = *(const uint32_t*)(smB + r0 + 8*KPITCH + c);
            qa_l[j][2] = *(const uint32_t*)(smB + r0 + c + 16);
            qa_l[j][3] = *(const uint32_t*)(smB + r0 + 8*KPITCH + c + 16);
        }
    }

    float O[8][4];
    #pragma unroll
    for (int i = 0; i < 8; i++) { O[i][0]=0.f; O[i][1]=0.f; O[i][2]=0.f; O[i][3]=0.f; }
    float ls0 = 0.f, ls1 = 0.f;
    uint32_t phi[16][2], plo[16][2];

    for (int it = 0; it < 16; it++) {
        const int m0g = it * 128;
        __syncthreads();                       // V smem (prev iter) done
        {   // stage K tile [128 m][64 d]
            const int m = t >> 1, half = (t & 1) * 32;
            const u16* ph = (const u16*)kh + ((size_t)bh*SEQ + m0g + m) * HD + half;
            const u16* pl = (const u16*)kl + ((size_t)bh*SEQ + m0g + m) * HD + half;
            #pragma unroll
            for (int u = 0; u < 4; u++) {
                *(uint4*)(smA + m*KPITCH + half*2 + 16*u) = *(const uint4*)(ph + 8*u);
                *(uint4*)(smB + m*KPITCH + half*2 + 16*u) = *(const uint4*)(pl + 8*u);
            }
        }
        __syncthreads();
        // S = Q K^T (3-term) -> exp -> P frags in registers
        #pragma unroll
        for (int mc = 0; mc < 16; mc++) {
            float s3[4] = {0.f,0.f,0.f,0.f};
            const int rb = (8*mc + g) * KPITCH;
            #pragma unroll
            for (int j = 0; j < 4; j++) {
                const int c = (16*j + 2*tt) * 2;
                uint32_t bh0 = *(const uint32_t*)(smA + rb + c);
                uint32_t bh1 = *(const uint32_t*)(smA + rb + c + 16);
                uint32_t bl0 = *(const uint32_t*)(smB + rb + c);
                uint32_t bl1 = *(const uint32_t*)(smB + rb + c + 16);
                mma16816(s3, qa_h[j], bh0, bh1);
                mma16816(s3, qa_h[j], bl0, bl1);
                mma16816(s3, qa_l[j], bh0, bh1);
            }
            float p0 = ex2f(s3[0] * SCL);
            float p1 = ex2f(s3[1] * SCL);
            float p2 = ex2f(s3[2] * SCL);
            float p3 = ex2f(s3[3] * SCL);
            ls0 += p0 + p1;
            ls1 += p2 + p3;
            split2(p0, p1, phi[mc][0], plo[mc][0]);
            split2(p2, p3, phi[mc][1], plo[mc][1]);
        }
        __syncthreads();
        {   // stage V tile [64 d][128 m]
            const int d = t >> 2, vm0 = (t & 3) * 32;
            const u16* ph = (const u16*)vh + ((size_t)bh*HD + d) * SEQ + m0g + vm0;
            const u16* pl = (const u16*)vl + ((size_t)bh*HD + d) * SEQ + m0g + vm0;
            #pragma unroll
            for (int u = 0; u < 4; u++) {
                *(uint4*)(smA + d*VPITCH + vm0*2 + 16*u) = *(const uint4*)(ph + 8*u);
                *(uint4*)(smB + d*VPITCH + vm0*2 + 16*u) = *(const uint4*)(pl + 8*u);
            }
        }
        __syncthreads();
        // O += P V^T (3-term)
        #pragma unroll
        for (int j = 0; j < 8; j++) {
            uint32_t ah[4] = { phi[2*j][0], phi[2*j][1], phi[2*j+1][0], phi[2*j+1][1] };
            uint32_t al[4] = { plo[2*j][0], plo[2*j][1], plo[2*j+1][0], plo[2*j+1][1] };
            #pragma unroll
            for (int dc = 0; dc < 8; dc++) {
                const int rb = (8*dc + g) * VPITCH + (16*j + 2*tt) * 2;
                uint32_t bh0 = *(const uint32_t*)(smA + rb);
                uint32_t bh1 = *(const uint32_t*)(smA + rb + 16);
                uint32_t bl0 = *(const uint32_t*)(smB + rb);
                uint32_t bl1 = *(const uint32_t*)(smB + rb + 16);
                mma16816(O[dc], ah, bh0, bh1);
                mma16816(O[dc], ah, bl0, bl1);
                mma16816(O[dc], al, bh0, bh1);
            }
        }
    }

    ls0 += __shfl_xor_sync(0xffffffffu, ls0, 1);
    ls0 += __shfl_xor_sync(0xffffffffu, ls0, 2);
    ls1 += __shfl_xor_sync(0xffffffffu, ls1, 1);
    ls1 += __shfl_xor_sync(0xffffffffu, ls1, 2);
    const float i0 = 1.f / ls0, i1 = 1.f / ls1;
    #pragma unroll
    for (int dc = 0; dc < 8; dc++) {
        const int d0 = 8*dc + 2*tt;
        float* xp = X + ((size_t)b*DM + 4*d0 + h) * SEQ + n0 + 16*w;
        xp[g]             = O[dc][0] * i0;
        xp[4*SEQ + g]     = O[dc][1] * i0;
        xp[g + 8]         = O[dc][2] * i1;
        xp[4*SEQ + g + 8] = O[dc][3] * i1;
    }
}

// ---------------------------------------------------------------------------
extern "C" void kernel_launch(void* const* d_in, const int* in_sizes, int n_in,
                              void* d_out, int out_size) {
    const float* query = (const float*)d_in[0];
    const float* key   = (const float*)d_in[1];
    const float* value = (const float*)d_in[2];
    const float* Wq = (const float*)d_in[3];
    const float* bq = (const float*)d_in[4];
    const float* Wk = (const float*)d_in[5];
    const float* bk = (const float*)d_in[6];
    const float* Wv = (const float*)d_in[7];
    const float* bv = (const float*)d_in[8];
    const float* Wm = (const float*)d_in[9];
    const float* bm = (const float*)d_in[10];

    __nv_bfloat16 *qh, *ql, *kh, *kl, *vh, *vl;
    float *x;
    cudaGetSymbolAddress((void**)&qh, g_qh);
    cudaGetSymbolAddress((void**)&ql, g_ql);
    cudaGetSymbolAddress((void**)&kh, g_kh);
    cudaGetSymbolAddress((void**)&kl, g_kl);
    cudaGetSymbolAddress((void**)&vh, g_vh);
    cudaGetSymbolAddress((void**)&vl, g_vl);
    cudaGetSymbolAddress((void**)&x,  g_x);

    dim3 pjGrid(SEQ/64, DM/64, BATCH);
    proj_kernel<1><<<pjGrid, 256>>>(Wq, bq, query, nullptr, qh, ql);
    proj_kernel<1><<<pjGrid, 256>>>(Wk, bk, key,   nullptr, kh, kl);
    proj_kernel<2><<<pjGrid, 256>>>(Wv, bv, value, nullptr, vh, vl);

    flash_kernel<<<dim3(SEQ/128, BH), 256>>>(qh, ql, kh, kl, vh, vl, x);

    proj_kernel<0><<<pjGrid, 256>>>(Wm, bm, x, (float*)d_out, nullptr, nullptr);
}

// round 5
// speedup vs baseline: 2.1030x; 1.0036x over previous
#include <cuda_runtime.h>
#include <cuda_bf16.h>
#include <cstdint>

#define BATCH 8
#define DM 256
#define NH 4
#define HD 64
#define SEQ 2048
#define BH (BATCH*NH)

typedef unsigned short u16;

// Q,K: [bh][n][d] hi/lo bf16 ; V: [bh][d][m] hi/lo ; X: [b][c][n] fp32
__device__ __nv_bfloat16 g_qh[(size_t)BH*SEQ*HD];
__device__ __nv_bfloat16 g_ql[(size_t)BH*SEQ*HD];
__device__ __nv_bfloat16 g_kh[(size_t)BH*SEQ*HD];
__device__ __nv_bfloat16 g_kl[(size_t)BH*SEQ*HD];
__device__ __nv_bfloat16 g_vh[(size_t)BH*HD*SEQ];
__device__ __nv_bfloat16 g_vl[(size_t)BH*HD*SEQ];
__device__ float         g_x [(size_t)BATCH*DM*SEQ];

__device__ __forceinline__ float ex2f(float x) {
    float r; asm("ex2.approx.f32 %0, %1;" : "=f"(r) : "f"(x)); return r;
}
__device__ __forceinline__ void split2(float v0, float v1, uint32_t& hp, uint32_t& lp) {
    asm("cvt.rn.bf16x2.f32 %0, %1, %2;" : "=r"(hp) : "f"(v1), "f"(v0));
    float f0 = __uint_as_float(hp << 16);
    float f1 = __uint_as_float(hp & 0xffff0000u);
    asm("cvt.rn.bf16x2.f32 %0, %1, %2;" : "=r"(lp) : "f"(v1 - f1), "f"(v0 - f0));
}
__device__ __forceinline__ void mma16816(float* d, const uint32_t* a, uint32_t b0, uint32_t b1) {
    asm volatile("mma.sync.aligned.m16n8k16.row.col.f32.bf16.bf16.f32 "
                 "{%0,%1,%2,%3}, {%4,%5,%6,%7}, {%8,%9}, {%0,%1,%2,%3};\n"
                 : "+f"(d[0]), "+f"(d[1]), "+f"(d[2]), "+f"(d[3])
                 : "r"(a[0]), "r"(a[1]), "r"(a[2]), "r"(a[3]), "r"(b0), "r"(b1));
}
__device__ __forceinline__ void cp16(uint32_t saddr, const void* g) {
    asm volatile("cp.async.ca.shared.global [%0], [%1], 16;" :: "r"(saddr), "l"(g));
}
#define CP_COMMIT() asm volatile("cp.async.commit_group;" ::: "memory")
#define CP_WAIT(n)  asm volatile("cp.async.wait_group %0;" :: "n"(n) : "memory")

// ---------------------------------------------------------------------------
// Projection: C[b][o][n] = sum_i W[o][i]*X[b][i][n] + bias[o]
// MODE 0: fp32 [b][o][n]; MODE 1: hi/lo bf16 [bh][n][d]; MODE 2: hi/lo [bh][d][m]
// ---------------------------------------------------------------------------
template<int MODE>
__global__ __launch_bounds__(256)
void proj_kernel(const float* __restrict__ W, const float* __restrict__ bias,
                 const float* __restrict__ X, float* __restrict__ C0,
                 __nv_bfloat16* __restrict__ Ch, __nv_bfloat16* __restrict__ Cl) {
    __shared__ float Ws[16][64];
    __shared__ float Xs[16][64];
    __shared__ u16 Th[64][68];
    __shared__ u16 Tl[64][68];
    const int n0 = blockIdx.x * 64, o0 = blockIdx.y * 64, b = blockIdx.z;
    const float* Xb = X + (size_t)b * DM * SEQ;
    const int tid = threadIdx.x;
    const int tx = tid & 15, ty = tid >> 4;
    const int wo = tid >> 2, wi = (tid & 3) * 4;
    const int xr = tid >> 6, xc = tid & 63;
    float acc[4][4] = {};
    for (int k0 = 0; k0 < DM; k0 += 16) {
        float4 wv = *(const float4*)&W[(o0 + wo) * DM + k0 + wi];
        Ws[wi+0][wo] = wv.x; Ws[wi+1][wo] = wv.y;
        Ws[wi+2][wo] = wv.z; Ws[wi+3][wo] = wv.w;
        #pragma unroll
        for (int r = 0; r < 4; r++)
            Xs[xr + 4*r][xc] = Xb[(size_t)(k0 + xr + 4*r) * SEQ + n0 + xc];
        __syncthreads();
        #pragma unroll
        for (int kk = 0; kk < 16; kk++) {
            float4 a  = *(const float4*)&Ws[kk][ty*4];
            float4 bb = *(const float4*)&Xs[kk][tx*4];
            float av[4] = {a.x, a.y, a.z, a.w};
            float bv[4] = {bb.x, bb.y, bb.z, bb.w};
            #pragma unroll
            for (int i = 0; i < 4; i++)
                #pragma unroll
                for (int j = 0; j < 4; j++)
                    acc[i][j] = fmaf(av[i], bv[j], acc[i][j]);
        }
        __syncthreads();
    }
    if (MODE == 0) {
        float* Cb = C0 + (size_t)b * DM * SEQ;
        #pragma unroll
        for (int i = 0; i < 4; i++) {
            float bi = bias[o0 + ty*4 + i];
            float4 o = make_float4(acc[i][0]+bi, acc[i][1]+bi, acc[i][2]+bi, acc[i][3]+bi);
            *(float4*)&Cb[(size_t)(o0 + ty*4 + i) * SEQ + n0 + tx*4] = o;
        }
    } else if (MODE == 1) {
        #pragma unroll
        for (int i = 0; i < 4; i++) {
            float bi = bias[o0 + ty*4 + i];
            #pragma unroll
            for (int j = 0; j < 4; j++) {
                float v = acc[i][j] + bi;
                __nv_bfloat16 hb = __float2bfloat16(v);
                __nv_bfloat16 lb = __float2bfloat16(v - __bfloat162float(hb));
                Th[tx*4+j][ty*4+i] = __bfloat16_as_ushort(hb);
                Tl[tx*4+j][ty*4+i] = __bfloat16_as_ushort(lb);
            }
        }
        __syncthreads();
        int n = tid & 63, hh = tid >> 6;
        u16 bh_[16], bl_[16];
        #pragma unroll
        for (int dd = 0; dd < 16; dd++) {
            bh_[dd] = Th[n][4*dd + hh];
            bl_[dd] = Tl[n][4*dd + hh];
        }
        size_t dst = ((size_t)(b*NH + hh) * SEQ + n0 + n) * HD + (o0 >> 2);
        *(uint4*)((u16*)Ch + dst)     = *(uint4*)bh_;
        *(uint4*)((u16*)Ch + dst + 8) = *(uint4*)(bh_ + 8);
        *(uint4*)((u16*)Cl + dst)     = *(uint4*)bl_;
        *(uint4*)((u16*)Cl + dst + 8) = *(uint4*)(bl_ + 8);
    } else {
        #pragma unroll
        for (int i = 0; i < 4; i++) {
            int o = o0 + ty*4 + i;
            float bi = bias[o];
            size_t base = ((size_t)(b*NH + (o & 3)) * HD + (o >> 2)) * SEQ + n0 + tx*4;
            uint32_t h01, l01, h23, l23;
            split2(acc[i][0]+bi, acc[i][1]+bi, h01, l01);
            split2(acc[i][2]+bi, acc[i][3]+bi, h23, l23);
            *(uint2*)((u16*)Ch + base) = make_uint2(h01, h23);
            *(uint2*)((u16*)Cl + base) = make_uint2(l01, l23);
        }
    }
}

// ---------------------------------------------------------------------------
// Fused flash attention, cp.async double-buffered K/V pipeline.
// 256 threads = 8 warps x 16 q-rows. Grid (SEQ/128, BH). Dynamic smem 140KB.
// ---------------------------------------------------------------------------
#define KPITCH 144
#define VPITCH 272
#define KH_OFF(s) ((s)*18432)
#define KL_OFF(s) (36864 + (s)*18432)
#define VH_OFF(s) (73728 + (s)*17408)
#define VL_OFF(s) (108544 + (s)*17408)
#define FLASH_SMEM 143360

__global__ __launch_bounds__(256)
void flash_kernel(const __nv_bfloat16* __restrict__ qh, const __nv_bfloat16* __restrict__ ql,
                  const __nv_bfloat16* __restrict__ kh, const __nv_bfloat16* __restrict__ kl,
                  const __nv_bfloat16* __restrict__ vh, const __nv_bfloat16* __restrict__ vl,
                  float* __restrict__ X) {
    extern __shared__ __align__(16) char sm[];
    const uint32_t sbase = (uint32_t)__cvta_generic_to_shared(sm);
    const int n0 = blockIdx.x * 128;
    const int bh = blockIdx.y;
    const int b = bh >> 2, h = bh & 3;
    const int t = threadIdx.x;
    const int w = t >> 5, l = t & 31;
    const int g = l >> 2, tt = l & 3;
    const float SCL = 0.125f * 1.44269504088896f;

    // copy maps: K/Q: row m (pitch 144B), 64B half per thread. V: row d (pitch 272B), 64B quarter.
    const int km = t >> 1, khalf = (t & 1) * 32;
    const int vd = t >> 2, vm0 = (t & 3) * 32;
    const uint32_t kso = (uint32_t)(km * KPITCH + khalf * 2);
    const uint32_t vso = (uint32_t)(vd * VPITCH + vm0 * 2);
    const u16* kgh = (const u16*)kh + ((size_t)bh*SEQ + km) * HD + khalf;
    const u16* kgl = (const u16*)kl + ((size_t)bh*SEQ + km) * HD + khalf;
    const u16* vgh = (const u16*)vh + ((size_t)bh*HD + vd) * SEQ + vm0;
    const u16* vgl = (const u16*)vl + ((size_t)bh*HD + vd) * SEQ + vm0;

    // ---- prologue: Q -> Kbuf0, K0 -> Kbuf1, V0 -> Vbuf0 (all cp.async)
    {
        const u16* qgh = (const u16*)qh + ((size_t)bh*SEQ + n0 + km) * HD + khalf;
        const u16* qgl = (const u16*)ql + ((size_t)bh*SEQ + n0 + km) * HD + khalf;
        #pragma unroll
        for (int u = 0; u < 4; u++) {
            cp16(sbase + KH_OFF(0) + kso + 16*u, qgh + 8*u);
            cp16(sbase + KL_OFF(0) + kso + 16*u, qgl + 8*u);
        }
        CP_COMMIT();
        #pragma unroll
        for (int u = 0; u < 4; u++) {
            cp16(sbase + KH_OFF(1) + kso + 16*u, kgh + 8*u);
            cp16(sbase + KL_OFF(1) + kso + 16*u, kgl + 8*u);
        }
        CP_COMMIT();
        #pragma unroll
        for (int u = 0; u < 4; u++) {
            cp16(sbase + VH_OFF(0) + vso + 16*u, vgh + 8*u);
            cp16(sbase + VL_OFF(0) + vso + 16*u, vgl + 8*u);
        }
        CP_COMMIT();
    }
    CP_WAIT(2);           // Q staged
    __syncthreads();

    uint32_t qa_h[4][4], qa_l[4][4];
    {
        const char* QH = sm + KH_OFF(0);
        const char* QL = sm + KL_OFF(0);
        const int r0 = (16*w + g) * KPITCH;
        #pragma unroll
        for (int j = 0; j < 4; j++) {
            const int c = (16*j + 2*tt) * 2;
            qa_h[j][0] = *(const uint32_t*)(QH + r0 + c);
            qa_h[j][1] = *(const uint32_t*)(QH + r0 + 8*KPITCH + c);
            qa_h[j][2] = *(const uint32_t*)(QH + r0 + c + 16);
            qa_h[j][3] = *(const uint32_t*)(QH + r0 + 8*KPITCH + c + 16);
            qa_l[j][0] = *(const uint32_t*)(QL + r0 + c);
            qa_l[j][1] = *(const uint32_t*)(QL + r0 + 8*KPITCH + c);
            qa_l[j][2] = *(const uint32_t*)(QL + r0 + c + 16);
            qa_l[j][3] = *(const uint32_t*)(QL + r0 + 8*KPITCH + c + 16);
        }
    }
    CP_WAIT(1);           // K0 staged
    __syncthreads();      // everyone done reading Q from Kbuf0

    float O[8][4];
    #pragma unroll
    for (int i = 0; i < 8; i++) { O[i][0]=0.f; O[i][1]=0.f; O[i][2]=0.f; O[i][3]=0.f; }
    float ls0 = 0.f, ls1 = 0.f;
    uint32_t phi[16][2], plo[16][2];

    for (int it = 0; it < 16; it++) {
        const int nx = (it + 1) & 15;          // wrap: iter 15 refetches tile 0 (harmless, uniform groups)
        // prefetch K(nx) into Kbuf[it&1]
        {
            const u16* ph = kgh + (size_t)nx * 128 * HD;
            const u16* pl = kgl + (size_t)nx * 128 * HD;
            const uint32_t dh = sbase + KH_OFF(it & 1) + kso;
            const uint32_t dl = sbase + KL_OFF(it & 1) + kso;
            #pragma unroll
            for (int u = 0; u < 4; u++) {
                cp16(dh + 16*u, ph + 8*u);
                cp16(dl + 16*u, pl + 8*u);
            }
            CP_COMMIT();
        }
        // ---- S = Q K^T (3-term) -> exp -> P frags, from Kbuf[(it+1)&1]
        {
            const char* KH = sm + KH_OFF((it + 1) & 1);
            const char* KL = sm + KL_OFF((it + 1) & 1);
            #pragma unroll
            for (int mc = 0; mc < 16; mc++) {
                float s3[4] = {0.f,0.f,0.f,0.f};
                const int rb = (8*mc + g) * KPITCH;
                #pragma unroll
                for (int j = 0; j < 4; j++) {
                    const int c = (16*j + 2*tt) * 2;
                    uint32_t bh0 = *(const uint32_t*)(KH + rb + c);
                    uint32_t bh1 = *(const uint32_t*)(KH + rb + c + 16);
                    uint32_t bl0 = *(const uint32_t*)(KL + rb + c);
                    uint32_t bl1 = *(const uint32_t*)(KL + rb + c + 16);
                    mma16816(s3, qa_h[j], bh0, bh1);
                    mma16816(s3, qa_h[j], bl0, bl1);
                    mma16816(s3, qa_l[j], bh0, bh1);
                }
                float p0 = ex2f(s3[0] * SCL);
                float p1 = ex2f(s3[1] * SCL);
                float p2 = ex2f(s3[2] * SCL);
                float p3 = ex2f(s3[3] * SCL);
                ls0 += p0 + p1;
                ls1 += p2 + p3;
                split2(p0, p1, phi[mc][0], plo[mc][0]);
                split2(p2, p3, phi[mc][1], plo[mc][1]);
            }
        }
        CP_WAIT(1);          // V(it) staged (K(nx) may still be in flight)
        __syncthreads();
        // prefetch V(nx) into Vbuf[(it+1)&1]
        {
            const u16* ph = vgh + (size_t)nx * 128;
            const u16* pl = vgl + (size_t)nx * 128;
            const uint32_t dh = sbase + VH_OFF((it + 1) & 1) + vso;
            const uint32_t dl = sbase + VL_OFF((it + 1) & 1) + vso;
            #pragma unroll
            for (int u = 0; u < 4; u++) {
                cp16(dh + 16*u, ph + 8*u);
                cp16(dl + 16*u, pl + 8*u);
            }
            CP_COMMIT();
        }
        // ---- O += P V^T (3-term), from Vbuf[it&1]
        {
            const char* VH = sm + VH_OFF(it & 1);
            const char* VL = sm + VL_OFF(it & 1);
            #pragma unroll
            for (int j = 0; j < 8; j++) {
                uint32_t ah[4] = { phi[2*j][0], phi[2*j][1], phi[2*j+1][0], phi[2*j+1][1] };
                uint32_t al[4] = { plo[2*j][0], plo[2*j][1], plo[2*j+1][0], plo[2*j+1][1] };
                #pragma unroll
                for (int dc = 0; dc < 8; dc++) {
                    const int rb = (8*dc + g) * VPITCH + (16*j + 2*tt) * 2;
                    uint32_t bh0 = *(const uint32_t*)(VH + rb);
                    uint32_t bh1 = *(const uint32_t*)(VH + rb + 16);
                    uint32_t bl0 = *(const uint32_t*)(VL + rb);
                    uint32_t bl1 = *(const uint32_t*)(VL + rb + 16);
                    mma16816(O[dc], ah, bh0, bh1);
                    mma16816(O[dc], ah, bl0, bl1);
                    mma16816(O[dc], al, bh0, bh1);
                }
            }
        }
        CP_WAIT(1);          // K(nx) staged
        __syncthreads();
    }

    ls0 += __shfl_xor_sync(0xffffffffu, ls0, 1);
    ls0 += __shfl_xor_sync(0xffffffffu, ls0, 2);
    ls1 += __shfl_xor_sync(0xffffffffu, ls1, 1);
    ls1 += __shfl_xor_sync(0xffffffffu, ls1, 2);
    const float i0 = 1.f / ls0, i1 = 1.f / ls1;
    #pragma unroll
    for (int dc = 0; dc < 8; dc++) {
        const int d0 = 8*dc + 2*tt;
        float* xp = X + ((size_t)b*DM + 4*d0 + h) * SEQ + n0 + 16*w;
        xp[g]             = O[dc][0] * i0;
        xp[4*SEQ + g]     = O[dc][1] * i0;
        xp[g + 8]         = O[dc][2] * i1;
        xp[4*SEQ + g + 8] = O[dc][3] * i1;
    }
}

// ---------------------------------------------------------------------------
extern "C" void kernel_launch(void* const* d_in, const int* in_sizes, int n_in,
                              void* d_out, int out_size) {
    const float* query = (const float*)d_in[0];
    const float* key   = (const float*)d_in[1];
    const float* value = (const float*)d_in[2];
    const float* Wq = (const float*)d_in[3];
    const float* bq = (const float*)d_in[4];
    const float* Wk = (const float*)d_in[5];
    const float* bk = (const float*)d_in[6];
    const float* Wv = (const float*)d_in[7];
    const float* bv = (const float*)d_in[8];
    const float* Wm = (const float*)d_in[9];
    const float* bm = (const float*)d_in[10];

    __nv_bfloat16 *qh, *ql, *kh, *kl, *vh, *vl;
    float *x;
    cudaGetSymbolAddress((void**)&qh, g_qh);
    cudaGetSymbolAddress((void**)&ql, g_ql);
    cudaGetSymbolAddress((void**)&kh, g_kh);
    cudaGetSymbolAddress((void**)&kl, g_kl);
    cudaGetSymbolAddress((void**)&vh, g_vh);
    cudaGetSymbolAddress((void**)&vl, g_vl);
    cudaGetSymbolAddress((void**)&x,  g_x);

    cudaFuncSetAttribute(flash_kernel, cudaFuncAttributeMaxDynamicSharedMemorySize, FLASH_SMEM);

    dim3 pjGrid(SEQ/64, DM/64, BATCH);
    proj_kernel<1><<<pjGrid, 256>>>(Wq, bq, query, nullptr, qh, ql);
    proj_kernel<1><<<pjGrid, 256>>>(Wk, bk, key,   nullptr, kh, kl);
    proj_kernel<2><<<pjGrid, 256>>>(Wv, bv, value, nullptr, vh, vl);

    flash_kernel<<<dim3(SEQ/128, BH), 256, FLASH_SMEM>>>(qh, ql, kh, kl, vh, vl, x);

    proj_kernel<0><<<pjGrid, 256>>>(Wm, bm, x, (float*)d_out, nullptr, nullptr);
}

// round 6
// speedup vs baseline: 2.1791x; 1.0362x over previous
#include <cuda_runtime.h>
#include <cuda_bf16.h>
#include <cstdint>

#define BATCH 8
#define DM 256
#define NH 4
#define HD 64
#define SEQ 2048
#define BH (BATCH*NH)

typedef unsigned short u16;

// Q,K: [bh][n][d] hi/lo bf16 ; V: [bh][d][m] hi/lo ; X: [b][c][n] fp32
__device__ __nv_bfloat16 g_qh[(size_t)BH*SEQ*HD];
__device__ __nv_bfloat16 g_ql[(size_t)BH*SEQ*HD];
__device__ __nv_bfloat16 g_kh[(size_t)BH*SEQ*HD];
__device__ __nv_bfloat16 g_kl[(size_t)BH*SEQ*HD];
__device__ __nv_bfloat16 g_vh[(size_t)BH*HD*SEQ];
__device__ __nv_bfloat16 g_vl[(size_t)BH*HD*SEQ];
__device__ float         g_x [(size_t)BATCH*DM*SEQ];

__device__ __forceinline__ float ex2f(float x) {
    float r; asm("ex2.approx.f32 %0, %1;" : "=f"(r) : "f"(x)); return r;
}
__device__ __forceinline__ void split2(float v0, float v1, uint32_t& hp, uint32_t& lp) {
    asm("cvt.rn.bf16x2.f32 %0, %1, %2;" : "=r"(hp) : "f"(v1), "f"(v0));
    float f0 = __uint_as_float(hp << 16);
    float f1 = __uint_as_float(hp & 0xffff0000u);
    asm("cvt.rn.bf16x2.f32 %0, %1, %2;" : "=r"(lp) : "f"(v1 - f1), "f"(v0 - f0));
}
__device__ __forceinline__ void mma16816(float* d, const uint32_t* a, uint32_t b0, uint32_t b1) {
    asm volatile("mma.sync.aligned.m16n8k16.row.col.f32.bf16.bf16.f32 "
                 "{%0,%1,%2,%3}, {%4,%5,%6,%7}, {%8,%9}, {%0,%1,%2,%3};\n"
                 : "+f"(d[0]), "+f"(d[1]), "+f"(d[2]), "+f"(d[3])
                 : "r"(a[0]), "r"(a[1]), "r"(a[2]), "r"(a[3]), "r"(b0), "r"(b1));
}
__device__ __forceinline__ void cp16(uint32_t saddr, const void* g) {
    asm volatile("cp.async.ca.shared.global [%0], [%1], 16;" :: "r"(saddr), "l"(g));
}
#define CP_COMMIT() asm volatile("cp.async.commit_group;" ::: "memory")
#define CP_WAIT(n)  asm volatile("cp.async.wait_group %0;" :: "n"(n) : "memory")

// ---------------------------------------------------------------------------
// Projection: C[b][o][n] = sum_i W[o][i]*X[b][i][n] + bias[o]
// MODE 0: fp32 [b][o][n]; MODE 1: hi/lo bf16 [bh][n][d]; MODE 2: hi/lo [bh][d][m]
// ---------------------------------------------------------------------------
template<int MODE>
__global__ __launch_bounds__(256)
void proj_kernel(const float* __restrict__ W, const float* __restrict__ bias,
                 const float* __restrict__ X, float* __restrict__ C0,
                 __nv_bfloat16* __restrict__ Ch, __nv_bfloat16* __restrict__ Cl) {
    __shared__ float Ws[16][64];
    __shared__ float Xs[16][64];
    __shared__ u16 Th[64][68];
    __shared__ u16 Tl[64][68];
    const int n0 = blockIdx.x * 64, o0 = blockIdx.y * 64, b = blockIdx.z;
    const float* Xb = X + (size_t)b * DM * SEQ;
    const int tid = threadIdx.x;
    const int tx = tid & 15, ty = tid >> 4;
    const int wo = tid >> 2, wi = (tid & 3) * 4;
    const int xr = tid >> 6, xc = tid & 63;
    float acc[4][4] = {};
    for (int k0 = 0; k0 < DM; k0 += 16) {
        float4 wv = *(const float4*)&W[(o0 + wo) * DM + k0 + wi];
        Ws[wi+0][wo] = wv.x; Ws[wi+1][wo] = wv.y;
        Ws[wi+2][wo] = wv.z; Ws[wi+3][wo] = wv.w;
        #pragma unroll
        for (int r = 0; r < 4; r++)
            Xs[xr + 4*r][xc] = Xb[(size_t)(k0 + xr + 4*r) * SEQ + n0 + xc];
        __syncthreads();
        #pragma unroll
        for (int kk = 0; kk < 16; kk++) {
            float4 a  = *(const float4*)&Ws[kk][ty*4];
            float4 bb = *(const float4*)&Xs[kk][tx*4];
            float av[4] = {a.x, a.y, a.z, a.w};
            float bv[4] = {bb.x, bb.y, bb.z, bb.w};
            #pragma unroll
            for (int i = 0; i < 4; i++)
                #pragma unroll
                for (int j = 0; j < 4; j++)
                    acc[i][j] = fmaf(av[i], bv[j], acc[i][j]);
        }
        __syncthreads();
    }
    if (MODE == 0) {
        float* Cb = C0 + (size_t)b * DM * SEQ;
        #pragma unroll
        for (int i = 0; i < 4; i++) {
            float bi = bias[o0 + ty*4 + i];
            float4 o = make_float4(acc[i][0]+bi, acc[i][1]+bi, acc[i][2]+bi, acc[i][3]+bi);
            *(float4*)&Cb[(size_t)(o0 + ty*4 + i) * SEQ + n0 + tx*4] = o;
        }
    } else if (MODE == 1) {
        #pragma unroll
        for (int i = 0; i < 4; i++) {
            float bi = bias[o0 + ty*4 + i];
            #pragma unroll
            for (int j = 0; j < 4; j++) {
                float v = acc[i][j] + bi;
                __nv_bfloat16 hb = __float2bfloat16(v);
                __nv_bfloat16 lb = __float2bfloat16(v - __bfloat162float(hb));
                Th[tx*4+j][ty*4+i] = __bfloat16_as_ushort(hb);
                Tl[tx*4+j][ty*4+i] = __bfloat16_as_ushort(lb);
            }
        }
        __syncthreads();
        int n = tid & 63, hh = tid >> 6;
        u16 bh_[16], bl_[16];
        #pragma unroll
        for (int dd = 0; dd < 16; dd++) {
            bh_[dd] = Th[n][4*dd + hh];
            bl_[dd] = Tl[n][4*dd + hh];
        }
        size_t dst = ((size_t)(b*NH + hh) * SEQ + n0 + n) * HD + (o0 >> 2);
        *(uint4*)((u16*)Ch + dst)     = *(uint4*)bh_;
        *(uint4*)((u16*)Ch + dst + 8) = *(uint4*)(bh_ + 8);
        *(uint4*)((u16*)Cl + dst)     = *(uint4*)bl_;
        *(uint4*)((u16*)Cl + dst + 8) = *(uint4*)(bl_ + 8);
    } else {
        #pragma unroll
        for (int i = 0; i < 4; i++) {
            int o = o0 + ty*4 + i;
            float bi = bias[o];
            size_t base = ((size_t)(b*NH + (o & 3)) * HD + (o >> 2)) * SEQ + n0 + tx*4;
            uint32_t h01, l01, h23, l23;
            split2(acc[i][0]+bi, acc[i][1]+bi, h01, l01);
            split2(acc[i][2]+bi, acc[i][3]+bi, h23, l23);
            *(uint2*)((u16*)Ch + base) = make_uint2(h01, h23);
            *(uint2*)((u16*)Cl + base) = make_uint2(l01, l23);
        }
    }
}

// ---------------------------------------------------------------------------
// Fused flash attention v3: single-buffered smem, 2 CTAs/SM for cross-CTA
// overlap; K-tile processed in two 64-m halves to halve P-frag registers.
// 256 threads = 8 warps x 16 q-rows. Grid (SEQ/128, BH). smem 70KB.
// ---------------------------------------------------------------------------
#define KPITCH 144
#define VPITCH 272
#define KH_OFF 0
#define KL_OFF 18432
#define VH_OFF 36864
#define VL_OFF 54272
#define FLASH_SMEM 71680

__global__ __launch_bounds__(256, 2)
void flash_kernel(const __nv_bfloat16* __restrict__ qh, const __nv_bfloat16* __restrict__ ql,
                  const __nv_bfloat16* __restrict__ kh, const __nv_bfloat16* __restrict__ kl,
                  const __nv_bfloat16* __restrict__ vh, const __nv_bfloat16* __restrict__ vl,
                  float* __restrict__ X) {
    extern __shared__ __align__(16) char sm[];
    const uint32_t sbase = (uint32_t)__cvta_generic_to_shared(sm);
    const int n0 = blockIdx.x * 128;
    const int bh = blockIdx.y;
    const int b = bh >> 2, h = bh & 3;
    const int t = threadIdx.x;
    const int w = t >> 5, l = t & 31;
    const int g = l >> 2, tt = l & 3;
    const float SCL = 0.125f * 1.44269504088896f;

    // copy maps
    const int km = t >> 1, khalf = (t & 1) * 32;
    const int vd = t >> 2, vm0 = (t & 3) * 32;
    const uint32_t kso = (uint32_t)(km * KPITCH + khalf * 2);
    const uint32_t vso = (uint32_t)(vd * VPITCH + vm0 * 2);
    const u16* kgh = (const u16*)kh + ((size_t)bh*SEQ + km) * HD + khalf;
    const u16* kgl = (const u16*)kl + ((size_t)bh*SEQ + km) * HD + khalf;
    const u16* vgh = (const u16*)vh + ((size_t)bh*HD + vd) * SEQ + vm0;
    const u16* vgl = (const u16*)vl + ((size_t)bh*HD + vd) * SEQ + vm0;

    // ---- prologue: Q -> K buffer, read A-frags, then release
    {
        const u16* qgh = (const u16*)qh + ((size_t)bh*SEQ + n0 + km) * HD + khalf;
        const u16* qgl = (const u16*)ql + ((size_t)bh*SEQ + n0 + km) * HD + khalf;
        #pragma unroll
        for (int u = 0; u < 4; u++) {
            cp16(sbase + KH_OFF + kso + 16*u, qgh + 8*u);
            cp16(sbase + KL_OFF + kso + 16*u, qgl + 8*u);
        }
        CP_COMMIT(); CP_WAIT(0);
    }
    __syncthreads();
    uint32_t qa_h[4][4], qa_l[4][4];
    {
        const char* QH = sm + KH_OFF;
        const char* QL = sm + KL_OFF;
        const int r0 = (16*w + g) * KPITCH;
        #pragma unroll
        for (int j = 0; j < 4; j++) {
            const int c = (16*j + 2*tt) * 2;
            qa_h[j][0] = *(const uint32_t*)(QH + r0 + c);
            qa_h[j][1] = *(const uint32_t*)(QH + r0 + 8*KPITCH + c);
            qa_h[j][2] = *(const uint32_t*)(QH + r0 + c + 16);
            qa_h[j][3] = *(const uint32_t*)(QH + r0 + 8*KPITCH + c + 16);
            qa_l[j][0] = *(const uint32_t*)(QL + r0 + c);
            qa_l[j][1] = *(const uint32_t*)(QL + r0 + 8*KPITCH + c);
            qa_l[j][2] = *(const uint32_t*)(QL + r0 + c + 16);
            qa_l[j][3] = *(const uint32_t*)(QL + r0 + 8*KPITCH + c + 16);
        }
    }
    __syncthreads();

    float O[8][4];
    #pragma unroll
    for (int i = 0; i < 8; i++) { O[i][0]=0.f; O[i][1]=0.f; O[i][2]=0.f; O[i][3]=0.f; }
    float ls0 = 0.f, ls1 = 0.f;
    uint32_t phi[8][2], plo[8][2];    // one 64-m half at a time

    for (int it = 0; it < 16; it++) {
        // ---- stage K(it) and V(it)
        {
            const u16* pkh = kgh + (size_t)it * 128 * HD;
            const u16* pkl = kgl + (size_t)it * 128 * HD;
            const u16* pvh = vgh + (size_t)it * 128;
            const u16* pvl = vgl + (size_t)it * 128;
            #pragma unroll
            for (int u = 0; u < 4; u++) {
                cp16(sbase + KH_OFF + kso + 16*u, pkh + 8*u);
                cp16(sbase + KL_OFF + kso + 16*u, pkl + 8*u);
                cp16(sbase + VH_OFF + vso + 16*u, pvh + 8*u);
                cp16(sbase + VL_OFF + vso + 16*u, pvl + 8*u);
            }
            CP_COMMIT(); CP_WAIT(0);
        }
        __syncthreads();

        #pragma unroll
        for (int half = 0; half < 2; half++) {
            // ---- S = Q K^T (3 short chains) -> exp -> P frags
            #pragma unroll
            for (int mc = 0; mc < 8; mc++) {
                float sa[4] = {0.f,0.f,0.f,0.f};
                float sb[4] = {0.f,0.f,0.f,0.f};
                float sc[4] = {0.f,0.f,0.f,0.f};
                const int rb = (64*half + 8*mc + g) * KPITCH;
                #pragma unroll
                for (int j = 0; j < 4; j++) {
                    const int c = (16*j + 2*tt) * 2;
                    uint32_t bh0 = *(const uint32_t*)(sm + KH_OFF + rb + c);
                    uint32_t bh1 = *(const uint32_t*)(sm + KH_OFF + rb + c + 16);
                    uint32_t bl0 = *(const uint32_t*)(sm + KL_OFF + rb + c);
                    uint32_t bl1 = *(const uint32_t*)(sm + KL_OFF + rb + c + 16);
                    mma16816(sa, qa_h[j], bh0, bh1);
                    mma16816(sb, qa_h[j], bl0, bl1);
                    mma16816(sc, qa_l[j], bh0, bh1);
                }
                float p0 = ex2f((sa[0] + sb[0] + sc[0]) * SCL);
                float p1 = ex2f((sa[1] + sb[1] + sc[1]) * SCL);
                float p2 = ex2f((sa[2] + sb[2] + sc[2]) * SCL);
                float p3 = ex2f((sa[3] + sb[3] + sc[3]) * SCL);
                ls0 += p0 + p1;
                ls1 += p2 + p3;
                split2(p0, p1, phi[mc][0], plo[mc][0]);
                split2(p2, p3, phi[mc][1], plo[mc][1]);
            }
            // ---- O += P V^T over this half's 64 m
            #pragma unroll
            for (int jj = 0; jj < 4; jj++) {
                uint32_t ah[4] = { phi[2*jj][0], phi[2*jj][1], phi[2*jj+1][0], phi[2*jj+1][1] };
                uint32_t al[4] = { plo[2*jj][0], plo[2*jj][1], plo[2*jj+1][0], plo[2*jj+1][1] };
                const int jcol = (16*(4*half + jj) + 2*tt) * 2;
                #pragma unroll
                for (int dc = 0; dc < 8; dc++) {
                    const int rb = (8*dc + g) * VPITCH + jcol;
                    uint32_t bh0 = *(const uint32_t*)(sm + VH_OFF + rb);
                    uint32_t bh1 = *(const uint32_t*)(sm + VH_OFF + rb + 16);
                    uint32_t bl0 = *(const uint32_t*)(sm + VL_OFF + rb);
                    uint32_t bl1 = *(const uint32_t*)(sm + VL_OFF + rb + 16);
                    mma16816(O[dc], ah, bh0, bh1);
                    mma16816(O[dc], ah, bl0, bl1);
                    mma16816(O[dc], al, bh0, bh1);
                }
            }
        }
        __syncthreads();   // everyone done reading K/V before next stage
    }

    ls0 += __shfl_xor_sync(0xffffffffu, ls0, 1);
    ls0 += __shfl_xor_sync(0xffffffffu, ls0, 2);
    ls1 += __shfl_xor_sync(0xffffffffu, ls1, 1);
    ls1 += __shfl_xor_sync(0xffffffffu, ls1, 2);
    const float i0 = 1.f / ls0, i1 = 1.f / ls1;
    #pragma unroll
    for (int dc = 0; dc < 8; dc++) {
        const int d0 = 8*dc + 2*tt;
        float* xp = X + ((size_t)b*DM + 4*d0 + h) * SEQ + n0 + 16*w;
        xp[g]             = O[dc][0] * i0;
        xp[4*SEQ + g]     = O[dc][1] * i0;
        xp[g + 8]         = O[dc][2] * i1;
        xp[4*SEQ + g + 8] = O[dc][3] * i1;
    }
}

// ---------------------------------------------------------------------------
extern "C" void kernel_launch(void* const* d_in, const int* in_sizes, int n_in,
                              void* d_out, int out_size) {
    const float* query = (const float*)d_in[0];
    const float* key   = (const float*)d_in[1];
    const float* value = (const float*)d_in[2];
    const float* Wq = (const float*)d_in[3];
    const float* bq = (const float*)d_in[4];
    const float* Wk = (const float*)d_in[5];
    const float* bk = (const float*)d_in[6];
    const float* Wv = (const float*)d_in[7];
    const float* bv = (const float*)d_in[8];
    const float* Wm = (const float*)d_in[9];
    const float* bm = (const float*)d_in[10];

    __nv_bfloat16 *qh, *ql, *kh, *kl, *vh, *vl;
    float *x;
    cudaGetSymbolAddress((void**)&qh, g_qh);
    cudaGetSymbolAddress((void**)&ql, g_ql);
    cudaGetSymbolAddress((void**)&kh, g_kh);
    cudaGetSymbolAddress((void**)&kl, g_kl);
    cudaGetSymbolAddress((void**)&vh, g_vh);
    cudaGetSymbolAddress((void**)&vl, g_vl);
    cudaGetSymbolAddress((void**)&x,  g_x);

    cudaFuncSetAttribute(flash_kernel, cudaFuncAttributeMaxDynamicSharedMemorySize, FLASH_SMEM);

    dim3 pjGrid(SEQ/64, DM/64, BATCH);
    proj_kernel<1><<<pjGrid, 256>>>(Wq, bq, query, nullptr, qh, ql);
    proj_kernel<1><<<pjGrid, 256>>>(Wk, bk, key,   nullptr, kh, kl);
    proj_kernel<2><<<pjGrid, 256>>>(Wv, bv, value, nullptr, vh, vl);

    flash_kernel<<<dim3(SEQ/128, BH), 256, FLASH_SMEM>>>(qh, ql, kh, kl, vh, vl, x);

    proj_kernel<0><<<pjGrid, 256>>>(Wm, bm, x, (float*)d_out, nullptr, nullptr);
}

// round 7
// speedup vs baseline: 2.9428x; 1.3505x over previous
#include <cuda_runtime.h>
#include <cuda_bf16.h>
#include <cstdint>

#define BATCH 8
#define DM 256
#define NH 4
#define HD 64
#define SEQ 2048
#define BH (BATCH*NH)

typedef unsigned short u16;

// Q,K: [bh][n][d] hi/lo bf16 ; V: [bh][d][m] hi/lo ; X: [b][c][n] fp32
__device__ __nv_bfloat16 g_qh[(size_t)BH*SEQ*HD];
__device__ __nv_bfloat16 g_ql[(size_t)BH*SEQ*HD];
__device__ __nv_bfloat16 g_kh[(size_t)BH*SEQ*HD];
__device__ __nv_bfloat16 g_kl[(size_t)BH*SEQ*HD];
__device__ __nv_bfloat16 g_vh[(size_t)BH*HD*SEQ];
__device__ __nv_bfloat16 g_vl[(size_t)BH*HD*SEQ];
__device__ float         g_x [(size_t)BATCH*DM*SEQ];

__device__ __forceinline__ float ex2f(float x) {
    float r; asm("ex2.approx.f32 %0, %1;" : "=f"(r) : "f"(x)); return r;
}
__device__ __forceinline__ void split2(float v0, float v1, uint32_t& hp, uint32_t& lp) {
    asm("cvt.rn.bf16x2.f32 %0, %1, %2;" : "=r"(hp) : "f"(v1), "f"(v0));
    float f0 = __uint_as_float(hp << 16);
    float f1 = __uint_as_float(hp & 0xffff0000u);
    asm("cvt.rn.bf16x2.f32 %0, %1, %2;" : "=r"(lp) : "f"(v1 - f1), "f"(v0 - f0));
}
__device__ __forceinline__ void mma16816(float* d, const uint32_t* a, uint32_t b0, uint32_t b1) {
    asm volatile("mma.sync.aligned.m16n8k16.row.col.f32.bf16.bf16.f32 "
                 "{%0,%1,%2,%3}, {%4,%5,%6,%7}, {%8,%9}, {%0,%1,%2,%3};\n"
                 : "+f"(d[0]), "+f"(d[1]), "+f"(d[2]), "+f"(d[3])
                 : "r"(a[0]), "r"(a[1]), "r"(a[2]), "r"(a[3]), "r"(b0), "r"(b1));
}
__device__ __forceinline__ void ldsm4(uint32_t a, uint32_t& r0, uint32_t& r1,
                                      uint32_t& r2, uint32_t& r3) {
    asm volatile("ldmatrix.sync.aligned.m8n8.x4.shared.b16 {%0,%1,%2,%3}, [%4];"
                 : "=r"(r0), "=r"(r1), "=r"(r2), "=r"(r3) : "r"(a));
}
__device__ __forceinline__ void ldsm4t(uint32_t a, uint32_t& r0, uint32_t& r1,
                                       uint32_t& r2, uint32_t& r3) {
    asm volatile("ldmatrix.sync.aligned.m8n8.x4.trans.shared.b16 {%0,%1,%2,%3}, [%4];"
                 : "=r"(r0), "=r"(r1), "=r"(r2), "=r"(r3) : "r"(a));
}
__device__ __forceinline__ void cp16(uint32_t saddr, const void* g) {
    asm volatile("cp.async.ca.shared.global [%0], [%1], 16;" :: "r"(saddr), "l"(g));
}
#define CP_COMMIT() asm volatile("cp.async.commit_group;" ::: "memory")
#define CP_WAIT(n)  asm volatile("cp.async.wait_group %0;" :: "n"(n) : "memory")

// ---------------------------------------------------------------------------
// Tensor-core projection: C[b][o][n] = sum_i W[o][i]*X[b][i][n] + bias[o]
// 3-term bf16 split via mma.sync. Tile: 128 o x 64 n, K=256 in 8 chunks of 32.
// MODE 0: fp32 [b][o][n]; MODE 1: hi/lo bf16 [bh][n][d]; MODE 2: hi/lo [bh][d][m]
// Grid (SEQ/64, DM/128, BATCH) = (32, 2, 8). 256 threads, 2 CTAs/SM.
// ---------------------------------------------------------------------------
#define PWH 0
#define PWL 9216
#define PXH 18432
#define PXL 23040
#define PSM_BYTES 34816   // epilogue Osm (128 x 68 f32) overlaps staging area

template<int MODE>
__global__ __launch_bounds__(256, 2)
void proj_tc(const float* __restrict__ W, const float* __restrict__ bias,
             const float* __restrict__ X, float* __restrict__ C0,
             __nv_bfloat16* __restrict__ Ch, __nv_bfloat16* __restrict__ Cl) {
    __shared__ __align__(16) char psm[PSM_BYTES];
    __shared__ float biasSm[128];
    const uint32_t sbase = (uint32_t)__cvta_generic_to_shared(psm);
    const int n0 = blockIdx.x * 64, o0 = blockIdx.y * 128, b = blockIdx.z;
    const int tid = threadIdx.x;
    const int w = tid >> 5, l = tid & 31;
    const int g = l >> 2, tt = l & 3;
    if (tid < 128) biasSm[tid] = bias[o0 + tid];

    float O[8][4];
    #pragma unroll
    for (int i = 0; i < 8; i++) { O[i][0]=0.f; O[i][1]=0.f; O[i][2]=0.f; O[i][3]=0.f; }

    // lane-constant ldmatrix.trans offset into X tiles:
    // lanes 0-7: b0(nb) rows k0-7 | 8-15: b1(nb) rows k8-15 | 16-23: b0(nb+1) | 24-31: b1(nb+1)
    const uint32_t xoff = (uint32_t)((8*((l >> 3) & 1) + (l & 7)) * 144 + 16 * (l >> 4));

    const int wi4 = (tid & 7) * 4;     // W stage: 4 consecutive i
    const int xn4 = (tid & 15) * 4;    // X stage: 4 consecutive n

    for (int c = 0; c < 8; c++) {
        const int k0 = c * 32;
        __syncthreads();
        // ---- stage W chunk [128 o][32 i] split hi/lo
        #pragma unroll
        for (int p = 0; p < 4; p++) {
            const int o = p * 32 + (tid >> 3);
            float4 v = *(const float4*)&W[(size_t)(o0 + o) * DM + k0 + wi4];
            uint32_t h01, l01, h23, l23;
            split2(v.x, v.y, h01, l01);
            split2(v.z, v.w, h23, l23);
            *(uint2*)(psm + PWH + o*72 + wi4*2) = make_uint2(h01, h23);
            *(uint2*)(psm + PWL + o*72 + wi4*2) = make_uint2(l01, l23);
        }
        // ---- stage X chunk [32 i][64 n] split hi/lo
        #pragma unroll
        for (int p = 0; p < 2; p++) {
            const int i = p * 16 + (tid >> 4);
            float4 v = *(const float4*)&X[((size_t)b * DM + k0 + i) * SEQ + n0 + xn4];
            uint32_t h01, l01, h23, l23;
            split2(v.x, v.y, h01, l01);
            split2(v.z, v.w, h23, l23);
            *(uint2*)(psm + PXH + i*144 + xn4*2) = make_uint2(h01, h23);
            *(uint2*)(psm + PXL + i*144 + xn4*2) = make_uint2(l01, l23);
        }
        __syncthreads();
        // ---- compute: 2 k16 slabs
        #pragma unroll
        for (int s = 0; s < 2; s++) {
            uint32_t ah[4], al[4];
            const char* wp = psm + PWH + (w*16 + g)*72 + s*32 + tt*4;
            ah[0] = *(const uint32_t*)wp;
            ah[1] = *(const uint32_t*)(wp + 8*72);
            ah[2] = *(const uint32_t*)(wp + 16);
            ah[3] = *(const uint32_t*)(wp + 8*72 + 16);
            const char* wq = wp + (PWL - PWH);
            al[0] = *(const uint32_t*)wq;
            al[1] = *(const uint32_t*)(wq + 8*72);
            al[2] = *(const uint32_t*)(wq + 16);
            al[3] = *(const uint32_t*)(wq + 8*72 + 16);
            const uint32_t xb = sbase + PXH + s*2304 + xoff;
            #pragma unroll
            for (int nbp = 0; nbp < 4; nbp++) {
                uint32_t h0,h1,h2,h3, q0,q1,q2,q3;
                ldsm4t(xb + 32*nbp,                 h0, h1, h2, h3);
                ldsm4t(xb + 32*nbp + (PXL - PXH),   q0, q1, q2, q3);
                mma16816(O[2*nbp],   ah, h0, h1);
                mma16816(O[2*nbp],   ah, q0, q1);
                mma16816(O[2*nbp],   al, h0, h1);
                mma16816(O[2*nbp+1], ah, h2, h3);
                mma16816(O[2*nbp+1], ah, q2, q3);
                mma16816(O[2*nbp+1], al, h2, h3);
            }
        }
    }
    __syncthreads();
    // ---- stage O into smem [128 o][68 pitch] fp32
    float* Osm = (float*)psm;
    {
        const int r = w*16 + g;
        #pragma unroll
        for (int nb = 0; nb < 8; nb++) {
            const int cc = nb*8 + 2*tt;
            Osm[r*68 + cc]       = O[nb][0];
            Osm[r*68 + cc + 1]   = O[nb][1];
            Osm[(r+8)*68 + cc]     = O[nb][2];
            Osm[(r+8)*68 + cc + 1] = O[nb][3];
        }
    }
    __syncthreads();

    if (MODE == 0) {
        const int o = tid >> 1, half = (tid & 1) * 32;
        const float bi = biasSm[o];
        const float* src = Osm + o*68 + half;
        float* dst = C0 + ((size_t)b * DM + o0 + o) * SEQ + n0 + half;
        #pragma unroll
        for (int j = 0; j < 8; j++) {
            float4 v = *(const float4*)(src + 4*j);
            v.x += bi; v.y += bi; v.z += bi; v.w += bi;
            *(float4*)(dst + 4*j) = v;
        }
    } else if (MODE == 1) {
        const int n = tid >> 2, hh = tid & 3;
        u16 oh[32], ol[32];
        #pragma unroll
        for (int d = 0; d < 32; d++) {
            float v = Osm[(4*d + hh)*68 + n] + biasSm[4*d + hh];
            __nv_bfloat16 hb = __float2bfloat16(v);
            __nv_bfloat16 lb = __float2bfloat16(v - __bfloat162float(hb));
            oh[d] = __bfloat16_as_ushort(hb);
            ol[d] = __bfloat16_as_ushort(lb);
        }
        size_t dst = ((size_t)(b*NH + hh) * SEQ + n0 + n) * HD + (o0 >> 2);
        #pragma unroll
        for (int j = 0; j < 4; j++) {
            *(uint4*)((u16*)Ch + dst + 8*j) = *(uint4*)(oh + 8*j);
            *(uint4*)((u16*)Cl + dst + 8*j) = *(uint4*)(ol + 8*j);
        }
    } else {
        const int ol_ = tid >> 1, mh = (tid & 1) * 32;
        const int chn = o0 + ol_;
        const int d = chn >> 2, hh = chn & 3;
        const float bi = biasSm[ol_];
        const float* src = Osm + ol_*68 + mh;
        u16 xh[32], xl[32];
        #pragma unroll
        for (int j = 0; j < 32; j++) {
            float v = src[j] + bi;
            __nv_bfloat16 hb = __float2bfloat16(v);
            __nv_bfloat16 lb = __float2bfloat16(v - __bfloat162float(hb));
            xh[j] = __bfloat16_as_ushort(hb);
            xl[j] = __bfloat16_as_ushort(lb);
        }
        size_t dst = ((size_t)(b*NH + hh) * HD + d) * SEQ + n0 + mh;
        #pragma unroll
        for (int j = 0; j < 4; j++) {
            *(uint4*)((u16*)Ch + dst + 8*j) = *(uint4*)(xh + 8*j);
            *(uint4*)((u16*)Cl + dst + 8*j) = *(uint4*)(xl + 8*j);
        }
    }
}

// ---------------------------------------------------------------------------
// Fused flash attention: single-buffered smem, 2 CTAs/SM, ldmatrix.x4 B-frags.
// 256 threads = 8 warps x 16 q-rows. Grid (SEQ/128, BH). smem 70KB.
// ---------------------------------------------------------------------------
#define KPITCH 144
#define VPITCH 272
#define KH_OFF 0
#define KL_OFF 18432
#define VH_OFF 36864
#define VL_OFF 54272
#define FLASH_SMEM 71680

__global__ __launch_bounds__(256, 2)
void flash_kernel(const __nv_bfloat16* __restrict__ qh, const __nv_bfloat16* __restrict__ ql,
                  const __nv_bfloat16* __restrict__ kh, const __nv_bfloat16* __restrict__ kl,
                  const __nv_bfloat16* __restrict__ vh, const __nv_bfloat16* __restrict__ vl,
                  float* __restrict__ X) {
    extern __shared__ __align__(16) char sm[];
    const uint32_t sbase = (uint32_t)__cvta_generic_to_shared(sm);
    const int n0 = blockIdx.x * 128;
    const int bh = blockIdx.y;
    const int b = bh >> 2, h = bh & 3;
    const int t = threadIdx.x;
    const int w = t >> 5, l = t & 31;
    const int g = l >> 2, tt = l & 3;
    const float SCL = 0.125f * 1.44269504088896f;

    // copy maps
    const int km = t >> 1, khalf = (t & 1) * 32;
    const int vd = t >> 2, vm0 = (t & 3) * 32;
    const uint32_t kso = (uint32_t)(km * KPITCH + khalf * 2);
    const uint32_t vso = (uint32_t)(vd * VPITCH + vm0 * 2);
    const u16* kgh = (const u16*)kh + ((size_t)bh*SEQ + km) * HD + khalf;
    const u16* kgl = (const u16*)kl + ((size_t)bh*SEQ + km) * HD + khalf;
    const u16* vgh = (const u16*)vh + ((size_t)bh*HD + vd) * SEQ + vm0;
    const u16* vgl = (const u16*)vl + ((size_t)bh*HD + vd) * SEQ + vm0;

    // ldmatrix lane-constant bases
    // K/S phase: mats = (j b0), (j b1), (j+1 b0), (j+1 b1) — contiguous 16B cols
    const uint32_t kfb = (uint32_t)((l & 7) * KPITCH + 16 * (l >> 3));
    const uint32_t kbaseH = sbase + KH_OFF + kfb;
    const uint32_t kbaseL = sbase + KL_OFF + kfb;
    // V/PV phase: mats = (dc b0), (dc b1), (dc+1 b0), (dc+1 b1)
    const uint32_t vfb = (uint32_t)(((l & 7) + 8*(l >> 4)) * VPITCH + 16 * ((l >> 3) & 1));
    const uint32_t vbaseH = sbase + VH_OFF + vfb;

    // ---- prologue: Q -> K buffer, read A-frags, then release
    {
        const u16* qgh = (const u16*)qh + ((size_t)bh*SEQ + n0 + km) * HD + khalf;
        const u16* qgl = (const u16*)ql + ((size_t)bh*SEQ + n0 + km) * HD + khalf;
        #pragma unroll
        for (int u = 0; u < 4; u++) {
            cp16(sbase + KH_OFF + kso + 16*u, qgh + 8*u);
            cp16(sbase + KL_OFF + kso + 16*u, qgl + 8*u);
        }
        CP_COMMIT(); CP_WAIT(0);
    }
    __syncthreads();
    uint32_t qa_h[4][4], qa_l[4][4];
    {
        const char* QH = sm + KH_OFF;
        const char* QL = sm + KL_OFF;
        const int r0 = (16*w + g) * KPITCH;
        #pragma unroll
        for (int j = 0; j < 4; j++) {
            const int c = (16*j + 2*tt) * 2;
            qa_h[j][0] = *(const uint32_t*)(QH + r0 + c);
            qa_h[j][1] = *(const uint32_t*)(QH + r0 + 8*KPITCH + c);
            qa_h[j][2] = *(const uint32_t*)(QH + r0 + c + 16);
            qa_h[j][3] = *(const uint32_t*)(QH + r0 + 8*KPITCH + c + 16);
            qa_l[j][0] = *(const uint32_t*)(QL + r0 + c);
            qa_l[j][1] = *(const uint32_t*)(QL + r0 + 8*KPITCH + c);
            qa_l[j][2] = *(const uint32_t*)(QL + r0 + c + 16);
            qa_l[j][3] = *(const uint32_t*)(QL + r0 + 8*KPITCH + c + 16);
        }
    }
    __syncthreads();

    float O[8][4];
    #pragma unroll
    for (int i = 0; i < 8; i++) { O[i][0]=0.f; O[i][1]=0.f; O[i][2]=0.f; O[i][3]=0.f; }
    float ls0 = 0.f, ls1 = 0.f;
    uint32_t phi[8][2], plo[8][2];

    for (int it = 0; it < 16; it++) {
        // ---- stage K(it) and V(it)
        {
            const u16* pkh = kgh + (size_t)it * 128 * HD;
            const u16* pkl = kgl + (size_t)it * 128 * HD;
            const u16* pvh = vgh + (size_t)it * 128;
            const u16* pvl = vgl + (size_t)it * 128;
            #pragma unroll
            for (int u = 0; u < 4; u++) {
                cp16(sbase + KH_OFF + kso + 16*u, pkh + 8*u);
                cp16(sbase + KL_OFF + kso + 16*u, pkl + 8*u);
                cp16(sbase + VH_OFF + vso + 16*u, pvh + 8*u);
                cp16(sbase + VL_OFF + vso + 16*u, pvl + 8*u);
            }
            CP_COMMIT(); CP_WAIT(0);
        }
        __syncthreads();

        #pragma unroll
        for (int half = 0; half < 2; half++) {
            // ---- S = Q K^T (3 short chains) -> exp -> P frags
            #pragma unroll
            for (int mc = 0; mc < 8; mc++) {
                float sa[4] = {0.f,0.f,0.f,0.f};
                float sb[4] = {0.f,0.f,0.f,0.f};
                float sc[4] = {0.f,0.f,0.f,0.f};
                const uint32_t rbase = (uint32_t)((64*half + 8*mc) * KPITCH);
                uint32_t bh_[8], bl_[8];
                ldsm4(kbaseH + rbase,      bh_[0], bh_[1], bh_[2], bh_[3]);
                ldsm4(kbaseH + rbase + 64, bh_[4], bh_[5], bh_[6], bh_[7]);
                ldsm4(kbaseL + rbase,      bl_[0], bl_[1], bl_[2], bl_[3]);
                ldsm4(kbaseL + rbase + 64, bl_[4], bl_[5], bl_[6], bl_[7]);
                #pragma unroll
                for (int j = 0; j < 4; j++) {
                    mma16816(sa, qa_h[j], bh_[2*j], bh_[2*j+1]);
                    mma16816(sb, qa_h[j], bl_[2*j], bl_[2*j+1]);
                    mma16816(sc, qa_l[j], bh_[2*j], bh_[2*j+1]);
                }
                float p0 = ex2f((sa[0] + sb[0] + sc[0]) * SCL);
                float p1 = ex2f((sa[1] + sb[1] + sc[1]) * SCL);
                float p2 = ex2f((sa[2] + sb[2] + sc[2]) * SCL);
                float p3 = ex2f((sa[3] + sb[3] + sc[3]) * SCL);
                ls0 += p0 + p1;
                ls1 += p2 + p3;
                split2(p0, p1, phi[mc][0], plo[mc][0]);
                split2(p2, p3, phi[mc][1], plo[mc][1]);
            }
            // ---- O += P V^T over this half's 64 m
            #pragma unroll
            for (int jj = 0; jj < 4; jj++) {
                uint32_t ah[4] = { phi[2*jj][0], phi[2*jj][1], phi[2*jj+1][0], phi[2*jj+1][1] };
                uint32_t al[4] = { plo[2*jj][0], plo[2*jj][1], plo[2*jj+1][0], plo[2*jj+1][1] };
                const uint32_t vcol = (uint32_t)(128*half + 32*jj);
                #pragma unroll
                for (int dcp = 0; dcp < 4; dcp++) {
                    const uint32_t addr = vbaseH + dcp*(16*VPITCH) + vcol;
                    uint32_t h0,h1,h2,h3, q0,q1,q2,q3;
                    ldsm4(addr,                       h0, h1, h2, h3);
                    ldsm4(addr + (VL_OFF - VH_OFF),   q0, q1, q2, q3);
                    mma16816(O[2*dcp],   ah, h0, h1);
                    mma16816(O[2*dcp],   ah, q0, q1);
                    mma16816(O[2*dcp],   al, h0, h1);
                    mma16816(O[2*dcp+1], ah, h2, h3);
                    mma16816(O[2*dcp+1], ah, q2, q3);
                    mma16816(O[2*dcp+1], al, h2, h3);
                }
            }
        }
        __syncthreads();   // everyone done reading K/V before next stage
    }

    ls0 += __shfl_xor_sync(0xffffffffu, ls0, 1);
    ls0 += __shfl_xor_sync(0xffffffffu, ls0, 2);
    ls1 += __shfl_xor_sync(0xffffffffu, ls1, 1);
    ls1 += __shfl_xor_sync(0xffffffffu, ls1, 2);
    const float i0 = 1.f / ls0, i1 = 1.f / ls1;
    #pragma unroll
    for (int dc = 0; dc < 8; dc++) {
        const int d0 = 8*dc + 2*tt;
        float* xp = X + ((size_t)b*DM + 4*d0 + h) * SEQ + n0 + 16*w;
        xp[g]             = O[dc][0] * i0;
        xp[4*SEQ + g]     = O[dc][1] * i0;
        xp[g + 8]         = O[dc][2] * i1;
        xp[4*SEQ + g + 8] = O[dc][3] * i1;
    }
}

// ---------------------------------------------------------------------------
extern "C" void kernel_launch(void* const* d_in, const int* in_sizes, int n_in,
                              void* d_out, int out_size) {
    const float* query = (const float*)d_in[0];
    const float* key   = (const float*)d_in[1];
    const float* value = (const float*)d_in[2];
    const float* Wq = (const float*)d_in[3];
    const float* bq = (const float*)d_in[4];
    const float* Wk = (const float*)d_in[5];
    const float* bk = (const float*)d_in[6];
    const float* Wv = (const float*)d_in[7];
    const float* bv = (const float*)d_in[8];
    const float* Wm = (const float*)d_in[9];
    const float* bm = (const float*)d_in[10];

    __nv_bfloat16 *qh, *ql, *kh, *kl, *vh, *vl;
    float *x;
    cudaGetSymbolAddress((void**)&qh, g_qh);
    cudaGetSymbolAddress((void**)&ql, g_ql);
    cudaGetSymbolAddress((void**)&kh, g_kh);
    cudaGetSymbolAddress((void**)&kl, g_kl);
    cudaGetSymbolAddress((void**)&vh, g_vh);
    cudaGetSymbolAddress((void**)&vl, g_vl);
    cudaGetSymbolAddress((void**)&x,  g_x);

    cudaFuncSetAttribute(flash_kernel, cudaFuncAttributeMaxDynamicSharedMemorySize, FLASH_SMEM);

    dim3 pjGrid(SEQ/64, DM/128, BATCH);
    proj_tc<1><<<pjGrid, 256>>>(Wq, bq, query, nullptr, qh, ql);
    proj_tc<1><<<pjGrid, 256>>>(Wk, bk, key,   nullptr, kh, kl);
    proj_tc<2><<<pjGrid, 256>>>(Wv, bv, value, nullptr, vh, vl);

    flash_kernel<<<dim3(SEQ/128, BH), 256, FLASH_SMEM>>>(qh, ql, kh, kl, vh, vl, x);

    proj_tc<0><<<pjGrid, 256>>>(Wm, bm, x, (float*)d_out, nullptr, nullptr);
}

// round 8
// speedup vs baseline: 3.8542x; 1.3097x over previous
#include <cuda_runtime.h>
#include <cuda_bf16.h>
#include <cuda_fp16.h>
#include <cstdint>

#define BATCH 8
#define DM 256
#define NH 4
#define HD 64
#define SEQ 2048
#define BH (BATCH*NH)

typedef unsigned short u16;

// Q: [bh][n][d] fp16 hi/lo ; K: [bh][m][d] fp16 hi ; V: [bh][d][m] fp16 hi
__device__ u16  g_qh[(size_t)BH*SEQ*HD];
__device__ u16  g_ql[(size_t)BH*SEQ*HD];
__device__ u16  g_kh[(size_t)BH*SEQ*HD];
__device__ u16  g_vh[(size_t)BH*HD*SEQ];
__device__ float g_x [(size_t)BATCH*DM*SEQ];

__device__ __forceinline__ float ex2f(float x) {
    float r; asm("ex2.approx.f32 %0, %1;" : "=f"(r) : "f"(x)); return r;
}
// bf16 split (used inside proj compute)
__device__ __forceinline__ void split2(float v0, float v1, uint32_t& hp, uint32_t& lp) {
    asm("cvt.rn.bf16x2.f32 %0, %1, %2;" : "=r"(hp) : "f"(v1), "f"(v0));
    float f0 = __uint_as_float(hp << 16);
    float f1 = __uint_as_float(hp & 0xffff0000u);
    asm("cvt.rn.bf16x2.f32 %0, %1, %2;" : "=r"(lp) : "f"(v1 - f1), "f"(v0 - f0));
}
// fp16 split, packed (v0 low, v1 high)
__device__ __forceinline__ void split2h(float v0, float v1, uint32_t& hp, uint32_t& lp) {
    asm("cvt.rn.f16x2.f32 %0, %1, %2;" : "=r"(hp) : "f"(v1), "f"(v0));
    float f0, f1;
    asm("{.reg .f16 a, b;\n\tmov.b32 {a, b}, %2;\n\tcvt.f32.f16 %0, a;\n\tcvt.f32.f16 %1, b;}"
        : "=f"(f0), "=f"(f1) : "r"(hp));
    asm("cvt.rn.f16x2.f32 %0, %1, %2;" : "=r"(lp) : "f"(v1 - f1), "f"(v0 - f0));
}
__device__ __forceinline__ void splithalf(float v, u16& h, u16& l) {
    __half hb = __float2half_rn(v);
    __half lb = __float2half_rn(v - __half2float(hb));
    h = __half_as_ushort(hb); l = __half_as_ushort(lb);
}
__device__ __forceinline__ void mma16816(float* d, const uint32_t* a, uint32_t b0, uint32_t b1) {
    asm volatile("mma.sync.aligned.m16n8k16.row.col.f32.bf16.bf16.f32 "
                 "{%0,%1,%2,%3}, {%4,%5,%6,%7}, {%8,%9}, {%0,%1,%2,%3};\n"
                 : "+f"(d[0]), "+f"(d[1]), "+f"(d[2]), "+f"(d[3])
                 : "r"(a[0]), "r"(a[1]), "r"(a[2]), "r"(a[3]), "r"(b0), "r"(b1));
}
__device__ __forceinline__ void mma16816h(float* d, const uint32_t* a, uint32_t b0, uint32_t b1) {
    asm volatile("mma.sync.aligned.m16n8k16.row.col.f32.f16.f16.f32 "
                 "{%0,%1,%2,%3}, {%4,%5,%6,%7}, {%8,%9}, {%0,%1,%2,%3};\n"
                 : "+f"(d[0]), "+f"(d[1]), "+f"(d[2]), "+f"(d[3])
                 : "r"(a[0]), "r"(a[1]), "r"(a[2]), "r"(a[3]), "r"(b0), "r"(b1));
}
__device__ __forceinline__ void ldsm4(uint32_t a, uint32_t& r0, uint32_t& r1,
                                      uint32_t& r2, uint32_t& r3) {
    asm volatile("ldmatrix.sync.aligned.m8n8.x4.shared.b16 {%0,%1,%2,%3}, [%4];"
                 : "=r"(r0), "=r"(r1), "=r"(r2), "=r"(r3) : "r"(a));
}
__device__ __forceinline__ void ldsm4t(uint32_t a, uint32_t& r0, uint32_t& r1,
                                       uint32_t& r2, uint32_t& r3) {
    asm volatile("ldmatrix.sync.aligned.m8n8.x4.trans.shared.b16 {%0,%1,%2,%3}, [%4];"
                 : "=r"(r0), "=r"(r1), "=r"(r2), "=r"(r3) : "r"(a));
}
__device__ __forceinline__ void cp16(uint32_t saddr, const void* g) {
    asm volatile("cp.async.ca.shared.global [%0], [%1], 16;" :: "r"(saddr), "l"(g));
}
#define CP_COMMIT() asm volatile("cp.async.commit_group;" ::: "memory")
#define CP_WAIT(n)  asm volatile("cp.async.wait_group %0;" :: "n"(n) : "memory")

// ---------------------------------------------------------------------------
// Tensor-core projection (bf16 3-term internally).
// MODE 0: fp32 [b][o][n]; MODE 1: fp16 hi/lo [bh][n][d] (Q);
// MODE 3: fp16 hi [bh][n][d] (K); MODE 2: fp16 hi [bh][d][m] (V).
// Grid (SEQ/64, DM/128, BATCH). 256 threads, 2 CTAs/SM.
// ---------------------------------------------------------------------------
#define PWH 0
#define PWL 9216
#define PXH 18432
#define PXL 23040
#define PSM_BYTES 34816

template<int MODE>
__global__ __launch_bounds__(256, 2)
void proj_tc(const float* __restrict__ W, const float* __restrict__ bias,
             const float* __restrict__ X, float* __restrict__ C0,
             u16* __restrict__ Ch, u16* __restrict__ Cl) {
    __shared__ __align__(16) char psm[PSM_BYTES];
    __shared__ float biasSm[128];
    const uint32_t sbase = (uint32_t)__cvta_generic_to_shared(psm);
    const int n0 = blockIdx.x * 64, o0 = blockIdx.y * 128, b = blockIdx.z;
    const int tid = threadIdx.x;
    const int w = tid >> 5, l = tid & 31;
    const int g = l >> 2, tt = l & 3;
    if (tid < 128) biasSm[tid] = bias[o0 + tid];

    float O[8][4];
    #pragma unroll
    for (int i = 0; i < 8; i++) { O[i][0]=0.f; O[i][1]=0.f; O[i][2]=0.f; O[i][3]=0.f; }

    const uint32_t xoff = (uint32_t)((8*((l >> 3) & 1) + (l & 7)) * 144 + 16 * (l >> 4));
    const int wi4 = (tid & 7) * 4;
    const int xn4 = (tid & 15) * 4;

    for (int c = 0; c < 8; c++) {
        const int k0 = c * 32;
        __syncthreads();
        #pragma unroll
        for (int p = 0; p < 4; p++) {
            const int o = p * 32 + (tid >> 3);
            float4 v = *(const float4*)&W[(size_t)(o0 + o) * DM + k0 + wi4];
            uint32_t h01, l01, h23, l23;
            split2(v.x, v.y, h01, l01);
            split2(v.z, v.w, h23, l23);
            *(uint2*)(psm + PWH + o*72 + wi4*2) = make_uint2(h01, h23);
            *(uint2*)(psm + PWL + o*72 + wi4*2) = make_uint2(l01, l23);
        }
        #pragma unroll
        for (int p = 0; p < 2; p++) {
            const int i = p * 16 + (tid >> 4);
            float4 v = *(const float4*)&X[((size_t)b * DM + k0 + i) * SEQ + n0 + xn4];
            uint32_t h01, l01, h23, l23;
            split2(v.x, v.y, h01, l01);
            split2(v.z, v.w, h23, l23);
            *(uint2*)(psm + PXH + i*144 + xn4*2) = make_uint2(h01, h23);
            *(uint2*)(psm + PXL + i*144 + xn4*2) = make_uint2(l01, l23);
        }
        __syncthreads();
        #pragma unroll
        for (int s = 0; s < 2; s++) {
            uint32_t ah[4], al[4];
            const char* wp = psm + PWH + (w*16 + g)*72 + s*32 + tt*4;
            ah[0] = *(const uint32_t*)wp;
            ah[1] = *(const uint32_t*)(wp + 8*72);
            ah[2] = *(const uint32_t*)(wp + 16);
            ah[3] = *(const uint32_t*)(wp + 8*72 + 16);
            const char* wq = wp + (PWL - PWH);
            al[0] = *(const uint32_t*)wq;
            al[1] = *(const uint32_t*)(wq + 8*72);
            al[2] = *(const uint32_t*)(wq + 16);
            al[3] = *(const uint32_t*)(wq + 8*72 + 16);
            const uint32_t xb = sbase + PXH + s*2304 + xoff;
            #pragma unroll
            for (int nbp = 0; nbp < 4; nbp++) {
                uint32_t h0,h1,h2,h3, q0,q1,q2,q3;
                ldsm4t(xb + 32*nbp,               h0, h1, h2, h3);
                ldsm4t(xb + 32*nbp + (PXL - PXH), q0, q1, q2, q3);
                mma16816(O[2*nbp],   ah, h0, h1);
                mma16816(O[2*nbp],   ah, q0, q1);
                mma16816(O[2*nbp],   al, h0, h1);
                mma16816(O[2*nbp+1], ah, h2, h3);
                mma16816(O[2*nbp+1], ah, q2, q3);
                mma16816(O[2*nbp+1], al, h2, h3);
            }
        }
    }
    __syncthreads();
    float* Osm = (float*)psm;
    {
        const int r = w*16 + g;
        #pragma unroll
        for (int nb = 0; nb < 8; nb++) {
            const int cc = nb*8 + 2*tt;
            Osm[r*68 + cc]         = O[nb][0];
            Osm[r*68 + cc + 1]     = O[nb][1];
            Osm[(r+8)*68 + cc]     = O[nb][2];
            Osm[(r+8)*68 + cc + 1] = O[nb][3];
        }
    }
    __syncthreads();

    if (MODE == 0) {
        const int o = tid >> 1, half = (tid & 1) * 32;
        const float bi = biasSm[o];
        const float* src = Osm + o*68 + half;
        float* dst = C0 + ((size_t)b * DM + o0 + o) * SEQ + n0 + half;
        #pragma unroll
        for (int j = 0; j < 8; j++) {
            float4 v = *(const float4*)(src + 4*j);
            v.x += bi; v.y += bi; v.z += bi; v.w += bi;
            *(float4*)(dst + 4*j) = v;
        }
    } else if (MODE == 1) {
        const int n = tid >> 2, hh = tid & 3;
        u16 oh[32], ol[32];
        #pragma unroll
        for (int d = 0; d < 32; d++)
            splithalf(Osm[(4*d + hh)*68 + n] + biasSm[4*d + hh], oh[d], ol[d]);
        size_t dst = ((size_t)(b*NH + hh) * SEQ + n0 + n) * HD + (o0 >> 2);
        #pragma unroll
        for (int j = 0; j < 4; j++) {
            *(uint4*)(Ch + dst + 8*j) = *(uint4*)(oh + 8*j);
            *(uint4*)(Cl + dst + 8*j) = *(uint4*)(ol + 8*j);
        }
    } else if (MODE == 3) {
        const int n = tid >> 2, hh = tid & 3;
        u16 oh[32];
        #pragma unroll
        for (int d = 0; d < 32; d++)
            oh[d] = __half_as_ushort(__float2half_rn(Osm[(4*d + hh)*68 + n] + biasSm[4*d + hh]));
        size_t dst = ((size_t)(b*NH + hh) * SEQ + n0 + n) * HD + (o0 >> 2);
        #pragma unroll
        for (int j = 0; j < 4; j++)
            *(uint4*)(Ch + dst + 8*j) = *(uint4*)(oh + 8*j);
    } else {
        const int ol_ = tid >> 1, mh = (tid & 1) * 32;
        const int chn = o0 + ol_;
        const int d = chn >> 2, hh = chn & 3;
        const float bi = biasSm[ol_];
        const float* src = Osm + ol_*68 + mh;
        u16 xh[32];
        #pragma unroll
        for (int j = 0; j < 32; j++)
            xh[j] = __half_as_ushort(__float2half_rn(src[j] + bi));
        size_t dst = ((size_t)(b*NH + hh) * HD + d) * SEQ + n0 + mh;
        #pragma unroll
        for (int j = 0; j < 4; j++)
            *(uint4*)(Ch + dst + 8*j) = *(uint4*)(xh + 8*j);
    }
}

// ---------------------------------------------------------------------------
// Fused flash attention, fp16 2-term, K/V hi-only, double-buffered cp.async.
// 256 threads = 8 warps x 16 q-rows. Grid (SEQ/128, BH). smem 106KB, 2 CTAs/SM.
// ---------------------------------------------------------------------------
#define KPITCH 144
#define VPITCH 272
#define STG 35840            // K (18432) + V (17408) per stage
#define QOFF 71680           // Q hi at QOFF, Q lo at QOFF+18432
#define FLASH_SMEM 108544

__global__ __launch_bounds__(256, 2)
void flash_kernel(const u16* __restrict__ qh, const u16* __restrict__ ql,
                  const u16* __restrict__ kh, const u16* __restrict__ vh,
                  float* __restrict__ X) {
    extern __shared__ __align__(16) char sm[];
    const uint32_t sbase = (uint32_t)__cvta_generic_to_shared(sm);
    const int n0 = blockIdx.x * 128;
    const int bh = blockIdx.y;
    const int b = bh >> 2, h = bh & 3;
    const int t = threadIdx.x;
    const int w = t >> 5, l = t & 31;
    const int g = l >> 2, tt = l & 3;
    const float SCL = 0.125f * 1.44269504088896f;

    // copy maps
    const int km = t >> 1, khalf = (t & 1) * 32;
    const int vd = t >> 2, vm0 = (t & 3) * 32;
    const uint32_t kso = (uint32_t)(km * KPITCH + khalf * 2);
    const uint32_t vso = (uint32_t)(vd * VPITCH + vm0 * 2);
    const u16* kg = kh + ((size_t)bh*SEQ + km) * HD + khalf;
    const u16* vg = vh + ((size_t)bh*HD + vd) * SEQ + vm0;

    // ldmatrix lane-constant bases
    const uint32_t kfb = (uint32_t)((l & 7) * KPITCH + 16 * (l >> 3));
    const uint32_t vfb = (uint32_t)(((l & 7) + 8*(l >> 4)) * VPITCH + 16 * ((l >> 3) & 1));

    // ---- prologue: Q (hi+lo), then K0/V0, K1/V1
    {
        const u16* qgh = qh + ((size_t)bh*SEQ + n0 + km) * HD + khalf;
        const u16* qgl = ql + ((size_t)bh*SEQ + n0 + km) * HD + khalf;
        #pragma unroll
        for (int u = 0; u < 4; u++) {
            cp16(sbase + QOFF + kso + 16*u,         qgh + 8*u);
            cp16(sbase + QOFF + 18432 + kso + 16*u, qgl + 8*u);
        }
        CP_COMMIT();
        #pragma unroll
        for (int u = 0; u < 4; u++) {
            cp16(sbase + kso + 16*u,         kg + 8*u);
            cp16(sbase + 18432 + vso + 16*u, vg + 8*u);
        }
        CP_COMMIT();
        #pragma unroll
        for (int u = 0; u < 4; u++) {
            cp16(sbase + STG + kso + 16*u,         kg + (size_t)128*HD + 8*u);
            cp16(sbase + STG + 18432 + vso + 16*u, vg + 128 + 8*u);
        }
        CP_COMMIT();
    }
    CP_WAIT(2);
    __syncthreads();
    uint32_t qa_h[4][4], qa_l[4][4];
    {
        const char* QH = sm + QOFF;
        const char* QL = sm + QOFF + 18432;
        const int r0 = (16*w + g) * KPITCH;
        #pragma unroll
        for (int j = 0; j < 4; j++) {
            const int c = (16*j + 2*tt) * 2;
            qa_h[j][0] = *(const uint32_t*)(QH + r0 + c);
            qa_h[j][1] = *(const uint32_t*)(QH + r0 + 8*KPITCH + c);
            qa_h[j][2] = *(const uint32_t*)(QH + r0 + c + 16);
            qa_h[j][3] = *(const uint32_t*)(QH + r0 + 8*KPITCH + c + 16);
            qa_l[j][0] = *(const uint32_t*)(QL + r0 + c);
            qa_l[j][1] = *(const uint32_t*)(QL + r0 + 8*KPITCH + c);
            qa_l[j][2] = *(const uint32_t*)(QL + r0 + c + 16);
            qa_l[j][3] = *(const uint32_t*)(QL + r0 + 8*KPITCH + c + 16);
        }
    }

    float O[8][4];
    #pragma unroll
    for (int i = 0; i < 8; i++) { O[i][0]=0.f; O[i][1]=0.f; O[i][2]=0.f; O[i][3]=0.f; }
    float ls0 = 0.f, ls1 = 0.f;
    uint32_t phi[8][2], plo[8][2];

    for (int it = 0; it < 16; it++) {
        if (it < 15) { CP_WAIT(1); } else { CP_WAIT(0); }
        __syncthreads();
        const uint32_t kb = sbase + (it & 1) * STG + kfb;
        const uint32_t vb = sbase + (it & 1) * STG + 18432 + vfb;

        #pragma unroll
        for (int half = 0; half < 2; half++) {
            // ---- S = (q_hi + q_lo) * k_hi -> exp -> P frags
            #pragma unroll
            for (int mc = 0; mc < 8; mc++) {
                float sa[4] = {0.f,0.f,0.f,0.f};
                float sb[4] = {0.f,0.f,0.f,0.f};
                const uint32_t rbase = (uint32_t)((64*half + 8*mc) * KPITCH);
                uint32_t bh_[8];
                ldsm4(kb + rbase,      bh_[0], bh_[1], bh_[2], bh_[3]);
                ldsm4(kb + rbase + 64, bh_[4], bh_[5], bh_[6], bh_[7]);
                #pragma unroll
                for (int j = 0; j < 4; j++) {
                    mma16816h(sa, qa_h[j], bh_[2*j], bh_[2*j+1]);
                    mma16816h(sb, qa_l[j], bh_[2*j], bh_[2*j+1]);
                }
                float p0 = ex2f((sa[0] + sb[0]) * SCL);
                float p1 = ex2f((sa[1] + sb[1]) * SCL);
                float p2 = ex2f((sa[2] + sb[2]) * SCL);
                float p3 = ex2f((sa[3] + sb[3]) * SCL);
                ls0 += p0 + p1;
                ls1 += p2 + p3;
                split2h(p0, p1, phi[mc][0], plo[mc][0]);
                split2h(p2, p3, phi[mc][1], plo[mc][1]);
            }
            // ---- O += (P_hi + P_lo) * v_hi
            #pragma unroll
            for (int jj = 0; jj < 4; jj++) {
                uint32_t ah[4] = { phi[2*jj][0], phi[2*jj][1], phi[2*jj+1][0], phi[2*jj+1][1] };
                uint32_t al[4] = { plo[2*jj][0], plo[2*jj][1], plo[2*jj+1][0], plo[2*jj+1][1] };
                const uint32_t vcol = (uint32_t)(128*half + 32*jj);
                #pragma unroll
                for (int dcp = 0; dcp < 4; dcp++) {
                    uint32_t h0,h1,h2,h3;
                    ldsm4(vb + dcp*(16*VPITCH) + vcol, h0, h1, h2, h3);
                    mma16816h(O[2*dcp],   ah, h0, h1);
                    mma16816h(O[2*dcp],   al, h0, h1);
                    mma16816h(O[2*dcp+1], ah, h2, h3);
                    mma16816h(O[2*dcp+1], al, h2, h3);
                }
            }
        }
        __syncthreads();   // all reads of buf[it&1] done
        if (it < 14) {     // stage (it+2) into buf[it&1]
            const u16* pk = kg + (size_t)(it + 2) * 128 * HD;
            const u16* pv = vg + (size_t)(it + 2) * 128;
            const uint32_t dk = sbase + (it & 1) * STG + kso;
            const uint32_t dv = sbase + (it & 1) * STG + 18432 + vso;
            #pragma unroll
            for (int u = 0; u < 4; u++) {
                cp16(dk + 16*u, pk + 8*u);
                cp16(dv + 16*u, pv + 8*u);
            }
            CP_COMMIT();
        }
    }

    ls0 += __shfl_xor_sync(0xffffffffu, ls0, 1);
    ls0 += __shfl_xor_sync(0xffffffffu, ls0, 2);
    ls1 += __shfl_xor_sync(0xffffffffu, ls1, 1);
    ls1 += __shfl_xor_sync(0xffffffffu, ls1, 2);
    const float i0 = 1.f / ls0, i1 = 1.f / ls1;
    #pragma unroll
    for (int dc = 0; dc < 8; dc++) {
        const int d0 = 8*dc + 2*tt;
        float* xp = X + ((size_t)b*DM + 4*d0 + h) * SEQ + n0 + 16*w;
        xp[g]             = O[dc][0] * i0;
        xp[4*SEQ + g]     = O[dc][1] * i0;
        xp[g + 8]         = O[dc][2] * i1;
        xp[4*SEQ + g + 8] = O[dc][3] * i1;
    }
}

// ---------------------------------------------------------------------------
extern "C" void kernel_launch(void* const* d_in, const int* in_sizes, int n_in,
                              void* d_out, int out_size) {
    const float* query = (const float*)d_in[0];
    const float* key   = (const float*)d_in[1];
    const float* value = (const float*)d_in[2];
    const float* Wq = (const float*)d_in[3];
    const float* bq = (const float*)d_in[4];
    const float* Wk = (const float*)d_in[5];
    const float* bk = (const float*)d_in[6];
    const float* Wv = (const float*)d_in[7];
    const float* bv = (const float*)d_in[8];
    const float* Wm = (const float*)d_in[9];
    const float* bm = (const float*)d_in[10];

    u16 *qh, *ql, *kh, *vh;
    float *x;
    cudaGetSymbolAddress((void**)&qh, g_qh);
    cudaGetSymbolAddress((void**)&ql, g_ql);
    cudaGetSymbolAddress((void**)&kh, g_kh);
    cudaGetSymbolAddress((void**)&vh, g_vh);
    cudaGetSymbolAddress((void**)&x,  g_x);

    cudaFuncSetAttribute(flash_kernel, cudaFuncAttributeMaxDynamicSharedMemorySize, FLASH_SMEM);

    dim3 pjGrid(SEQ/64, DM/128, BATCH);
    proj_tc<1><<<pjGrid, 256>>>(Wq, bq, query, nullptr, qh, ql);
    proj_tc<3><<<pjGrid, 256>>>(Wk, bk, key,   nullptr, kh, nullptr);
    proj_tc<2><<<pjGrid, 256>>>(Wv, bv, value, nullptr, vh, nullptr);

    flash_kernel<<<dim3(SEQ/128, BH), 256, FLASH_SMEM>>>(qh, ql, kh, vh, x);

    proj_tc<0><<<pjGrid, 256>>>(Wm, bm, x, (float*)d_out, nullptr, nullptr);
}

// round 9
// speedup vs baseline: 4.5184x; 1.1723x over previous
#include <cuda_runtime.h>
#include <cuda_bf16.h>
#include <cuda_fp16.h>
#include <cstdint>

#define BATCH 8
#define DM 256
#define NH 4
#define HD 64
#define SEQ 2048
#define BH (BATCH*NH)

typedef unsigned short u16;

// Q: [bh][n][d] fp16 hi/lo (pre-scaled by 0.125*log2e) ; K: [bh][m][d] fp16 ; V: [bh][d][m] fp16
__device__ u16  g_qh[(size_t)BH*SEQ*HD];
__device__ u16  g_ql[(size_t)BH*SEQ*HD];
__device__ u16  g_kh[(size_t)BH*SEQ*HD];
__device__ u16  g_vh[(size_t)BH*HD*SEQ];
__device__ float g_x [(size_t)BATCH*DM*SEQ];

#define QSCALE 0.18033688011112042f   // 0.125 * log2(e)

__device__ __forceinline__ float ex2f(float x) {
    float r; asm("ex2.approx.f32 %0, %1;" : "=f"(r) : "f"(x)); return r;
}
__device__ __forceinline__ uint32_t packh2(float lo, float hi) {
    uint32_t r; asm("cvt.rn.f16x2.f32 %0, %1, %2;" : "=r"(r) : "f"(hi), "f"(lo)); return r;
}
// bf16 split (used inside proj compute)
__device__ __forceinline__ void split2(float v0, float v1, uint32_t& hp, uint32_t& lp) {
    asm("cvt.rn.bf16x2.f32 %0, %1, %2;" : "=r"(hp) : "f"(v1), "f"(v0));
    float f0 = __uint_as_float(hp << 16);
    float f1 = __uint_as_float(hp & 0xffff0000u);
    asm("cvt.rn.bf16x2.f32 %0, %1, %2;" : "=r"(lp) : "f"(v1 - f1), "f"(v0 - f0));
}
__device__ __forceinline__ void splithalf(float v, u16& h, u16& l) {
    __half hb = __float2half_rn(v);
    __half lb = __float2half_rn(v - __half2float(hb));
    h = __half_as_ushort(hb); l = __half_as_ushort(lb);
}
__device__ __forceinline__ void mma16816(float* d, const uint32_t* a, uint32_t b0, uint32_t b1) {
    asm volatile("mma.sync.aligned.m16n8k16.row.col.f32.bf16.bf16.f32 "
                 "{%0,%1,%2,%3}, {%4,%5,%6,%7}, {%8,%9}, {%0,%1,%2,%3};\n"
                 : "+f"(d[0]), "+f"(d[1]), "+f"(d[2]), "+f"(d[3])
                 : "r"(a[0]), "r"(a[1]), "r"(a[2]), "r"(a[3]), "r"(b0), "r"(b1));
}
__device__ __forceinline__ void mma16816h(float* d, const uint32_t* a, uint32_t b0, uint32_t b1) {
    asm volatile("mma.sync.aligned.m16n8k16.row.col.f32.f16.f16.f32 "
                 "{%0,%1,%2,%3}, {%4,%5,%6,%7}, {%8,%9}, {%0,%1,%2,%3};\n"
                 : "+f"(d[0]), "+f"(d[1]), "+f"(d[2]), "+f"(d[3])
                 : "r"(a[0]), "r"(a[1]), "r"(a[2]), "r"(a[3]), "r"(b0), "r"(b1));
}
__device__ __forceinline__ void ldsm4(uint32_t a, uint32_t& r0, uint32_t& r1,
                                      uint32_t& r2, uint32_t& r3) {
    asm volatile("ldmatrix.sync.aligned.m8n8.x4.shared.b16 {%0,%1,%2,%3}, [%4];"
                 : "=r"(r0), "=r"(r1), "=r"(r2), "=r"(r3) : "r"(a));
}
__device__ __forceinline__ void ldsm4t(uint32_t a, uint32_t& r0, uint32_t& r1,
                                       uint32_t& r2, uint32_t& r3) {
    asm volatile("ldmatrix.sync.aligned.m8n8.x4.trans.shared.b16 {%0,%1,%2,%3}, [%4];"
                 : "=r"(r0), "=r"(r1), "=r"(r2), "=r"(r3) : "r"(a));
}
__device__ __forceinline__ void cp16(uint32_t saddr, const void* g) {
    asm volatile("cp.async.ca.shared.global [%0], [%1], 16;" :: "r"(saddr), "l"(g));
}
#define CP_COMMIT() asm volatile("cp.async.commit_group;" ::: "memory")
#define CP_WAIT(n)  asm volatile("cp.async.wait_group %0;" :: "n"(n) : "memory")

// ---------------------------------------------------------------------------
// Tensor-core projection (bf16 3-term internally).
// MODE 0: fp32 [b][o][n]; MODE 1: fp16 hi/lo [bh][n][d], pre-scaled (Q);
// MODE 3: fp16 hi [bh][n][d] (K); MODE 2: fp16 hi [bh][d][m] (V).
// Grid (SEQ/64, DM/128, BATCH). 256 threads, 2 CTAs/SM.
// ---------------------------------------------------------------------------
#define PWH 0
#define PWL 9216
#define PXH 18432
#define PXL 23040
#define PSM_BYTES 34816

template<int MODE>
__global__ __launch_bounds__(256, 2)
void proj_tc(const float* __restrict__ W, const float* __restrict__ bias,
             const float* __restrict__ X, float* __restrict__ C0,
             u16* __restrict__ Ch, u16* __restrict__ Cl) {
    __shared__ __align__(16) char psm[PSM_BYTES];
    __shared__ float biasSm[128];
    const uint32_t sbase = (uint32_t)__cvta_generic_to_shared(psm);
    const int n0 = blockIdx.x * 64, o0 = blockIdx.y * 128, b = blockIdx.z;
    const int tid = threadIdx.x;
    const int w = tid >> 5, l = tid & 31;
    const int g = l >> 2, tt = l & 3;
    if (tid < 128) biasSm[tid] = bias[o0 + tid];

    float O[8][4];
    #pragma unroll
    for (int i = 0; i < 8; i++) { O[i][0]=0.f; O[i][1]=0.f; O[i][2]=0.f; O[i][3]=0.f; }

    const uint32_t xoff = (uint32_t)((8*((l >> 3) & 1) + (l & 7)) * 144 + 16 * (l >> 4));
    const int wi4 = (tid & 7) * 4;
    const int xn4 = (tid & 15) * 4;

    for (int c = 0; c < 8; c++) {
        const int k0 = c * 32;
        __syncthreads();
        #pragma unroll
        for (int p = 0; p < 4; p++) {
            const int o = p * 32 + (tid >> 3);
            float4 v = *(const float4*)&W[(size_t)(o0 + o) * DM + k0 + wi4];
            uint32_t h01, l01, h23, l23;
            split2(v.x, v.y, h01, l01);
            split2(v.z, v.w, h23, l23);
            *(uint2*)(psm + PWH + o*72 + wi4*2) = make_uint2(h01, h23);
            *(uint2*)(psm + PWL + o*72 + wi4*2) = make_uint2(l01, l23);
        }
        #pragma unroll
        for (int p = 0; p < 2; p++) {
            const int i = p * 16 + (tid >> 4);
            float4 v = *(const float4*)&X[((size_t)b * DM + k0 + i) * SEQ + n0 + xn4];
            uint32_t h01, l01, h23, l23;
            split2(v.x, v.y, h01, l01);
            split2(v.z, v.w, h23, l23);
            *(uint2*)(psm + PXH + i*144 + xn4*2) = make_uint2(h01, h23);
            *(uint2*)(psm + PXL + i*144 + xn4*2) = make_uint2(l01, l23);
        }
        __syncthreads();
        #pragma unroll
        for (int s = 0; s < 2; s++) {
            uint32_t ah[4], al[4];
            const char* wp = psm + PWH + (w*16 + g)*72 + s*32 + tt*4;
            ah[0] = *(const uint32_t*)wp;
            ah[1] = *(const uint32_t*)(wp + 8*72);
            ah[2] = *(const uint32_t*)(wp + 16);
            ah[3] = *(const uint32_t*)(wp + 8*72 + 16);
            const char* wq = wp + (PWL - PWH);
            al[0] = *(const uint32_t*)wq;
            al[1] = *(const uint32_t*)(wq + 8*72);
            al[2] = *(const uint32_t*)(wq + 16);
            al[3] = *(const uint32_t*)(wq + 8*72 + 16);
            const uint32_t xb = sbase + PXH + s*2304 + xoff;
            #pragma unroll
            for (int nbp = 0; nbp < 4; nbp++) {
                uint32_t h0,h1,h2,h3, q0,q1,q2,q3;
                ldsm4t(xb + 32*nbp,               h0, h1, h2, h3);
                ldsm4t(xb + 32*nbp + (PXL - PXH), q0, q1, q2, q3);
                mma16816(O[2*nbp],   ah, h0, h1);
                mma16816(O[2*nbp],   ah, q0, q1);
                mma16816(O[2*nbp],   al, h0, h1);
                mma16816(O[2*nbp+1], ah, h2, h3);
                mma16816(O[2*nbp+1], ah, q2, q3);
                mma16816(O[2*nbp+1], al, h2, h3);
            }
        }
    }
    __syncthreads();
    float* Osm = (float*)psm;
    {
        const int r = w*16 + g;
        #pragma unroll
        for (int nb = 0; nb < 8; nb++) {
            const int cc = nb*8 + 2*tt;
            Osm[r*68 + cc]         = O[nb][0];
            Osm[r*68 + cc + 1]     = O[nb][1];
            Osm[(r+8)*68 + cc]     = O[nb][2];
            Osm[(r+8)*68 + cc + 1] = O[nb][3];
        }
    }
    __syncthreads();

    if (MODE == 0) {
        const int o = tid >> 1, half = (tid & 1) * 32;
        const float bi = biasSm[o];
        const float* src = Osm + o*68 + half;
        float* dst = C0 + ((size_t)b * DM + o0 + o) * SEQ + n0 + half;
        #pragma unroll
        for (int j = 0; j < 8; j++) {
            float4 v = *(const float4*)(src + 4*j);
            v.x += bi; v.y += bi; v.z += bi; v.w += bi;
            *(float4*)(dst + 4*j) = v;
        }
    } else if (MODE == 1) {
        const int n = tid >> 2, hh = tid & 3;
        u16 oh[32], ol[32];
        #pragma unroll
        for (int d = 0; d < 32; d++)
            splithalf((Osm[(4*d + hh)*68 + n] + biasSm[4*d + hh]) * QSCALE, oh[d], ol[d]);
        size_t dst = ((size_t)(b*NH + hh) * SEQ + n0 + n) * HD + (o0 >> 2);
        #pragma unroll
        for (int j = 0; j < 4; j++) {
            *(uint4*)(Ch + dst + 8*j) = *(uint4*)(oh + 8*j);
            *(uint4*)(Cl + dst + 8*j) = *(uint4*)(ol + 8*j);
        }
    } else if (MODE == 3) {
        const int n = tid >> 2, hh = tid & 3;
        u16 oh[32];
        #pragma unroll
        for (int d = 0; d < 32; d++)
            oh[d] = __half_as_ushort(__float2half_rn(Osm[(4*d + hh)*68 + n] + biasSm[4*d + hh]));
        size_t dst = ((size_t)(b*NH + hh) * SEQ + n0 + n) * HD + (o0 >> 2);
        #pragma unroll
        for (int j = 0; j < 4; j++)
            *(uint4*)(Ch + dst + 8*j) = *(uint4*)(oh + 8*j);
    } else {
        const int ol_ = tid >> 1, mh = (tid & 1) * 32;
        const int chn = o0 + ol_;
        const int d = chn >> 2, hh = chn & 3;
        const float bi = biasSm[ol_];
        const float* src = Osm + ol_*68 + mh;
        u16 xh[32];
        #pragma unroll
        for (int j = 0; j < 32; j++)
            xh[j] = __half_as_ushort(__float2half_rn(src[j] + bi));
        size_t dst = ((size_t)(b*NH + hh) * HD + d) * SEQ + n0 + mh;
        #pragma unroll
        for (int j = 0; j < 4; j++)
            *(uint4*)(Ch + dst + 8*j) = *(uint4*)(xh + 8*j);
    }
}

// ---------------------------------------------------------------------------
// Fused flash attention: fp16, Q 2-term (pre-scaled), K/V/P single-term,
// ls via all-ones MMA. Double-buffered cp.async. 2 CTAs/SM.
// 256 threads = 8 warps x 16 q-rows. Grid (SEQ/128, BH). smem 106KB.
// ---------------------------------------------------------------------------
#define KPITCH 144
#define VPITCH 272
#define STG 35840            // K (18432) + V (17408) per stage
#define QOFF 71680           // Q hi at QOFF, Q lo at QOFF+18432
#define FLASH_SMEM 108544

__global__ __launch_bounds__(256, 2)
void flash_kernel(const u16* __restrict__ qh, const u16* __restrict__ ql,
                  const u16* __restrict__ kh, const u16* __restrict__ vh,
                  float* __restrict__ X) {
    extern __shared__ __align__(16) char sm[];
    const uint32_t sbase = (uint32_t)__cvta_generic_to_shared(sm);
    const int n0 = blockIdx.x * 128;
    const int bh = blockIdx.y;
    const int b = bh >> 2, h = bh & 3;
    const int t = threadIdx.x;
    const int w = t >> 5, l = t & 31;
    const int g = l >> 2, tt = l & 3;
    const uint32_t ONES = 0x3C003C00u;

    // copy maps
    const int km = t >> 1, khalf = (t & 1) * 32;
    const int vd = t >> 2, vm0 = (t & 3) * 32;
    const uint32_t kso = (uint32_t)(km * KPITCH + khalf * 2);
    const uint32_t vso = (uint32_t)(vd * VPITCH + vm0 * 2);
    const u16* kg = kh + ((size_t)bh*SEQ + km) * HD + khalf;
    const u16* vg = vh + ((size_t)bh*HD + vd) * SEQ + vm0;

    // ldmatrix lane-constant bases
    const uint32_t kfb = (uint32_t)((l & 7) * KPITCH + 16 * (l >> 3));
    const uint32_t vfb = (uint32_t)(((l & 7) + 8*(l >> 4)) * VPITCH + 16 * ((l >> 3) & 1));

    // ---- prologue: Q (hi+lo), then K0/V0, K1/V1
    {
        const u16* qgh = qh + ((size_t)bh*SEQ + n0 + km) * HD + khalf;
        const u16* qgl = ql + ((size_t)bh*SEQ + n0 + km) * HD + khalf;
        #pragma unroll
        for (int u = 0; u < 4; u++) {
            cp16(sbase + QOFF + kso + 16*u,         qgh + 8*u);
            cp16(sbase + QOFF + 18432 + kso + 16*u, qgl + 8*u);
        }
        CP_COMMIT();
        #pragma unroll
        for (int u = 0; u < 4; u++) {
            cp16(sbase + kso + 16*u,         kg + 8*u);
            cp16(sbase + 18432 + vso + 16*u, vg + 8*u);
        }
        CP_COMMIT();
        #pragma unroll
        for (int u = 0; u < 4; u++) {
            cp16(sbase + STG + kso + 16*u,         kg + (size_t)128*HD + 8*u);
            cp16(sbase + STG + 18432 + vso + 16*u, vg + 128 + 8*u);
        }
        CP_COMMIT();
    }
    CP_WAIT(2);
    __syncthreads();
    uint32_t qa_h[4][4], qa_l[4][4];
    {
        const char* QH = sm + QOFF;
        const char* QL = sm + QOFF + 18432;
        const int r0 = (16*w + g) * KPITCH;
        #pragma unroll
        for (int j = 0; j < 4; j++) {
            const int c = (16*j + 2*tt) * 2;
            qa_h[j][0] = *(const uint32_t*)(QH + r0 + c);
            qa_h[j][1] = *(const uint32_t*)(QH + r0 + 8*KPITCH + c);
            qa_h[j][2] = *(const uint32_t*)(QH + r0 + c + 16);
            qa_h[j][3] = *(const uint32_t*)(QH + r0 + 8*KPITCH + c + 16);
            qa_l[j][0] = *(const uint32_t*)(QL + r0 + c);
            qa_l[j][1] = *(const uint32_t*)(QL + r0 + 8*KPITCH + c);
            qa_l[j][2] = *(const uint32_t*)(QL + r0 + c + 16);
            qa_l[j][3] = *(const uint32_t*)(QL + r0 + 8*KPITCH + c + 16);
        }
    }

    float O[8][4];
    #pragma unroll
    for (int i = 0; i < 8; i++) { O[i][0]=0.f; O[i][1]=0.f; O[i][2]=0.f; O[i][3]=0.f; }
    float lsacc[4] = {0.f, 0.f, 0.f, 0.f};
    uint32_t phi[8][2];

    for (int it = 0; it < 16; it++) {
        if (it < 15) { CP_WAIT(1); } else { CP_WAIT(0); }
        __syncthreads();
        const uint32_t kb = sbase + (it & 1) * STG + kfb;
        const uint32_t vb = sbase + (it & 1) * STG + 18432 + vfb;

        #pragma unroll
        for (int half = 0; half < 2; half++) {
            // ---- S = (q_hi + q_lo) * k  (exponent already in log2 units) -> P
            #pragma unroll
            for (int mc = 0; mc < 8; mc++) {
                float sa[4] = {0.f,0.f,0.f,0.f};
                float sb[4] = {0.f,0.f,0.f,0.f};
                const uint32_t rbase = (uint32_t)((64*half + 8*mc) * KPITCH);
                uint32_t bh_[8];
                ldsm4(kb + rbase,      bh_[0], bh_[1], bh_[2], bh_[3]);
                ldsm4(kb + rbase + 64, bh_[4], bh_[5], bh_[6], bh_[7]);
                #pragma unroll
                for (int j = 0; j < 4; j++) {
                    mma16816h(sa, qa_h[j], bh_[2*j], bh_[2*j+1]);
                    mma16816h(sb, qa_l[j], bh_[2*j], bh_[2*j+1]);
                }
                float p0 = ex2f(sa[0] + sb[0]);
                float p1 = ex2f(sa[1] + sb[1]);
                float p2 = ex2f(sa[2] + sb[2]);
                float p3 = ex2f(sa[3] + sb[3]);
                phi[mc][0] = packh2(p0, p1);
                phi[mc][1] = packh2(p2, p3);
            }
            // ---- O += P * v ; ls += P * 1
            #pragma unroll
            for (int jj = 0; jj < 4; jj++) {
                uint32_t ah[4] = { phi[2*jj][0], phi[2*jj][1], phi[2*jj+1][0], phi[2*jj+1][1] };
                mma16816h(lsacc, ah, ONES, ONES);
                const uint32_t vcol = (uint32_t)(128*half + 32*jj);
                #pragma unroll
                for (int dcp = 0; dcp < 4; dcp++) {
                    uint32_t h0,h1,h2,h3;
                    ldsm4(vb + dcp*(16*VPITCH) + vcol, h0, h1, h2, h3);
                    mma16816h(O[2*dcp],   ah, h0, h1);
                    mma16816h(O[2*dcp+1], ah, h2, h3);
                }
            }
        }
        __syncthreads();   // all reads of buf[it&1] done
        if (it < 14) {     // stage (it+2) into buf[it&1]
            const u16* pk = kg + (size_t)(it + 2) * 128 * HD;
            const u16* pv = vg + (size_t)(it + 2) * 128;
            const uint32_t dk = sbase + (it & 1) * STG + kso;
            const uint32_t dv = sbase + (it & 1) * STG + 18432 + vso;
            #pragma unroll
            for (int u = 0; u < 4; u++) {
                cp16(dk + 16*u, pk + 8*u);
                cp16(dv + 16*u, pv + 8*u);
            }
            CP_COMMIT();
        }
    }

    // lsacc[0] = row (16w+g) sum; lsacc[2] = row (16w+g+8) sum (all lanes agree per row-group)
    const float i0 = 1.f / lsacc[0], i1 = 1.f / lsacc[2];
    #pragma unroll
    for (int dc = 0; dc < 8; dc++) {
        const int d0 = 8*dc + 2*tt;
        float* xp = X + ((size_t)b*DM + 4*d0 + h) * SEQ + n0 + 16*w;
        xp[g]             = O[dc][0] * i0;
        xp[4*SEQ + g]     = O[dc][1] * i0;
        xp[g + 8]         = O[dc][2] * i1;
        xp[4*SEQ + g + 8] = O[dc][3] * i1;
    }
}

// ---------------------------------------------------------------------------
extern "C" void kernel_launch(void* const* d_in, const int* in_sizes, int n_in,
                              void* d_out, int out_size) {
    const float* query = (const float*)d_in[0];
    const float* key   = (const float*)d_in[1];
    const float* value = (const float*)d_in[2];
    const float* Wq = (const float*)d_in[3];
    const float* bq = (const float*)d_in[4];
    const float* Wk = (const float*)d_in[5];
    const float* bk = (const float*)d_in[6];
    const float* Wv = (const float*)d_in[7];
    const float* bv = (const float*)d_in[8];
    const float* Wm = (const float*)d_in[9];
    const float* bm = (const float*)d_in[10];

    u16 *qh, *ql, *kh, *vh;
    float *x;
    cudaGetSymbolAddress((void**)&qh, g_qh);
    cudaGetSymbolAddress((void**)&ql, g_ql);
    cudaGetSymbolAddress((void**)&kh, g_kh);
    cudaGetSymbolAddress((void**)&vh, g_vh);
    cudaGetSymbolAddress((void**)&x,  g_x);

    cudaFuncSetAttribute(flash_kernel, cudaFuncAttributeMaxDynamicSharedMemorySize, FLASH_SMEM);

    dim3 pjGrid(SEQ/64, DM/128, BATCH);
    proj_tc<1><<<pjGrid, 256>>>(Wq, bq, query, nullptr, qh, ql);
    proj_tc<3><<<pjGrid, 256>>>(Wk, bk, key,   nullptr, kh, nullptr);
    proj_tc<2><<<pjGrid, 256>>>(Wv, bv, value, nullptr, vh, nullptr);

    flash_kernel<<<dim3(SEQ/128, BH), 256, FLASH_SMEM>>>(qh, ql, kh, vh, x);

    proj_tc<0><<<pjGrid, 256>>>(Wm, bm, x, (float*)d_out, nullptr, nullptr);
}